// round 12
// baseline (speedup 1.0000x reference)
#include <cuda_runtime.h>
#include <cuda_bf16.h>
#include <cstdint>

#define N_NODES_C 50000
#define N_EDGES_C 25000
#define MAX_ARITY 6
#define MAX_DEG 8
#define BATCH_C 4096

// ---------------- scratch (device globals; no allocations allowed) ----------------
__device__ __align__(256) __nv_bfloat16 g_embn[N_NODES_C * 128];
__device__ __align__(256) __nv_bfloat16 g_embe[N_EDGES_C * 128];
__device__ __align__(256) __nv_bfloat16 g_hn1[N_NODES_C * 256];
__device__ __align__(256) __nv_bfloat16 g_eo1[N_EDGES_C * 256];
__device__ __align__(256) __nv_bfloat16 g_no1[N_NODES_C * 256];
__device__ __align__(256) __nv_bfloat16 g_hn2[N_NODES_C * 128];
__device__ __align__(256) float g_eo2[N_EDGES_C * 128];
__device__ __align__(256) float g_no2[N_NODES_C * 128];
// pre-transposed bf16 weights, [n][k] (node projections only)
__device__ __align__(256) __nv_bfloat16 g_Bt1n[256 * 128];
__device__ __align__(256) __nv_bfloat16 g_Bt2n[128 * 256];
// score-weight vectors for node-GEMM epilogues
__device__ float g_wpn1[256];
__device__ float g_wqn1[256];
__device__ float g_wpn2[128];
__device__ float g_wqn2[128];
// collapsed edge-score GEMV vectors (fp32): v = B @ w
__device__ float g_vpe1[512];   // [h][k]: sum_j We[h][k][j]*a1[h][j]
__device__ float g_vpe2[256];   // [k]:    sum_j We_o[k][j]*a1_o[j]
// scalar score caches
__device__ float g_pn1[N_NODES_C * 4];
__device__ float g_sn1[N_NODES_C * 4];
__device__ float g_se1[N_EDGES_C * 4];
__device__ float g_pe1[N_EDGES_C * 4];
__device__ float g_pn2[N_NODES_C];
__device__ float g_sn2[N_NODES_C];
__device__ float g_se2[N_EDGES_C];
__device__ float g_pe2[N_EDGES_C];
__device__ unsigned char g_mask[N_NODES_C];

// ---------------- helpers ----------------
__device__ __forceinline__ float warp_sum(float v) {
#pragma unroll
    for (int o = 16; o > 0; o >>= 1) v += __shfl_xor_sync(0xffffffffu, v, o);
    return v;
}
__device__ __forceinline__ float seg8_sum(float v) {
#pragma unroll
    for (int o = 4; o > 0; o >>= 1) v += __shfl_xor_sync(0xffffffffu, v, o);
    return v;
}
__device__ __forceinline__ float eluf(float x)  { return x > 0.f ? x : expm1f(x); }
__device__ __forceinline__ float lreluf(float x){ return x > 0.f ? x : 0.2f * x; }

__device__ __forceinline__ void ldsm4(unsigned r[4], unsigned addr) {
    asm volatile("ldmatrix.sync.aligned.m8n8.x4.shared.b16 {%0,%1,%2,%3},[%4];"
                 : "=r"(r[0]), "=r"(r[1]), "=r"(r[2]), "=r"(r[3]) : "r"(addr));
}
__device__ __forceinline__ void mma16(float c[4], const unsigned a[4],
                                      unsigned b0, unsigned b1) {
    asm volatile(
        "mma.sync.aligned.m16n8k16.row.col.f32.bf16.bf16.f32 "
        "{%0,%1,%2,%3},{%4,%5,%6,%7},{%8,%9},{%0,%1,%2,%3};"
        : "+f"(c[0]), "+f"(c[1]), "+f"(c[2]), "+f"(c[3])
        : "r"(a[0]), "r"(a[1]), "r"(a[2]), "r"(a[3]), "r"(b0), "r"(b1));
}

__device__ __forceinline__ unsigned packbf(float a, float b) {
    __nv_bfloat162 h = __floats2bfloat162_rn(a, b);
    return *reinterpret_cast<unsigned*>(&h);
}
__device__ __forceinline__ float2 unpackbf(unsigned u) {
    return __bfloat1622float2(*reinterpret_cast<__nv_bfloat162*>(&u));
}
__device__ __forceinline__ void unpack8(uint4 u, float f[8]) {
    float2 a = unpackbf(u.x), b = unpackbf(u.y), c = unpackbf(u.z), d = unpackbf(u.w);
    f[0] = a.x; f[1] = a.y; f[2] = b.x; f[3] = b.y;
    f[4] = c.x; f[5] = c.y; f[6] = d.x; f[7] = d.y;
}
__device__ __forceinline__ uint4 pack8(const float f[8]) {
    uint4 u;
    u.x = packbf(f[0], f[1]); u.y = packbf(f[2], f[3]);
    u.z = packbf(f[4], f[5]); u.w = packbf(f[6], f[7]);
    return u;
}

// ---------------- prep ----------------
__global__ void prep(const float* __restrict__ Wn, const float* __restrict__ We,
                     const float* __restrict__ Wn_o,
                     const float* __restrict__ a1, const float* __restrict__ a2,
                     const float* __restrict__ a1o, const float* __restrict__ a2o,
                     const float* __restrict__ We_o) {
    int i = blockIdx.x * 256 + threadIdx.x;
    if (i < 32768) {
        int c = i >> 7, k = i & 127;
        int h = c >> 6, j = c & 63;
        g_Bt1n[i] = __float2bfloat16_rn(Wn[h * 8192 + k * 64 + j]);
        int n2 = i >> 8, k2 = i & 255;
        g_Bt2n[i] = __float2bfloat16_rn(Wn_o[k2 * 128 + n2]);
    }
    if (i < 256) {
        int h = i >> 6, j = i & 63;
        g_wpn1[i] = a1[h * 128 + 64 + j];
        g_wqn1[i] = a2[h * 128 + j];
    }
    if (i < 128) {
        g_wpn2[i] = a1o[128 + i];
        g_wqn2[i] = a2o[i];
    }
    // GEMV vectors (fp32)
    if (i < 512) {
        int h = i >> 7, k = i & 127;
        float s = 0.f;
#pragma unroll 8
        for (int j = 0; j < 64; j++) s += We[h * 8192 + k * 64 + j] * a1[h * 128 + j];
        g_vpe1[i] = s;
    }
    if (i < 256) {
        float s = 0.f;
#pragma unroll 8
        for (int j = 0; j < 128; j++) s += We_o[i * 128 + j] * a1o[j];
        g_vpe2[i] = s;
    }
    if (i < N_NODES_C) g_mask[i] = 0;
}

// ---------------- convert embeddings fp32 -> bf16 ----------------
__global__ void conv_emb(const float* __restrict__ nemb, const float* __restrict__ eemb) {
    int i = blockIdx.x * 256 + threadIdx.x;
    if (i < (N_NODES_C * 128) / 8) {
        float4 v0 = *reinterpret_cast<const float4*>(nemb + i * 8);
        float4 v1 = *reinterpret_cast<const float4*>(nemb + i * 8 + 4);
        uint4 u;
        u.x = packbf(v0.x, v0.y); u.y = packbf(v0.z, v0.w);
        u.z = packbf(v1.x, v1.y); u.w = packbf(v1.z, v1.w);
        *reinterpret_cast<uint4*>(g_embn + i * 8) = u;
    }
    if (i < (N_EDGES_C * 128) / 8) {
        float4 v0 = *reinterpret_cast<const float4*>(eemb + i * 8);
        float4 v1 = *reinterpret_cast<const float4*>(eemb + i * 8 + 4);
        uint4 u;
        u.x = packbf(v0.x, v0.y); u.y = packbf(v0.z, v0.w);
        u.z = packbf(v1.x, v1.y); u.w = packbf(v1.z, v1.w);
        *reinterpret_cast<uint4*>(g_embe + i * 8) = u;
    }
}

// ---------------- mark batch-referenced nodes ----------------
__global__ void mark_nodes(const int* __restrict__ bi) {
    int i = blockIdx.x * 256 + threadIdx.x;
    if (i >= BATCH_C * 6) return;
    int b = i / 6, a = i % 6 + 1;
    int nid = bi[b * 7 + a] - 1;
    if (nid < 0) nid += N_NODES_C;
    g_mask[nid] = 1;
}

// ---------------- GEMV: layer1 edge scores se1[e,h] = embe[e,:] . vpe1[h,:] ------
__global__ __launch_bounds__(256)
void gemv_se1() {
    int e = blockIdx.x * 8 + (threadIdx.x >> 5);
    if (e >= N_EDGES_C) return;
    int lane = threadIdx.x & 31;
    uint2 u = *reinterpret_cast<const uint2*>(g_embe + (size_t)e * 128 + lane * 4);
    float2 x = unpackbf(u.x), y = unpackbf(u.y);
    float f[4] = {x.x, x.y, y.x, y.y};
    float p[4];
#pragma unroll
    for (int h = 0; h < 4; h++) {
        float s = 0.f;
#pragma unroll
        for (int i = 0; i < 4; i++) s += f[i] * g_vpe1[h * 128 + lane * 4 + i];
        p[h] = warp_sum(s);
    }
    if (lane == 0)
        *reinterpret_cast<float4*>(g_se1 + e * 4) = make_float4(p[0], p[1], p[2], p[3]);
}

// ---------------- GEMV: layer2 edge scores se2[e] = ELU(eo1[e,:]) . vpe2 ---------
__global__ __launch_bounds__(256)
void gemv_se2() {
    int e = blockIdx.x * 8 + (threadIdx.x >> 5);
    if (e >= N_EDGES_C) return;
    int lane = threadIdx.x & 31;
    uint4 u = *reinterpret_cast<const uint4*>(g_eo1 + (size_t)e * 256 + lane * 8);
    float f[8]; unpack8(u, f);
    float s = 0.f;
#pragma unroll
    for (int i = 0; i < 8; i++) s += eluf(f[i]) * g_vpe2[lane * 8 + i];
    s = warp_sum(s);
    if (lane == 0) g_se2[e] = s;
}

// ---------------- BF16 GEMM (node projections): BM=128, BN=128, 6-stage ----------
struct GArgs {
    const __nv_bfloat16* A;
    const __nv_bfloat16* Bt;
    __nv_bfloat16* C;
    int M;
    const float* wp;
    const float* wq;
    float* P;
    float* Q;
    int gx;       // blocks in x
};

__global__ __launch_bounds__(256, 2)
void gemm_nd(GArgs ga, int N, int K, int PS) {
    extern __shared__ __align__(16) __nv_bfloat16 smem[];
    __nv_bfloat16* Asm = smem;                    // [6][128][24]
    __nv_bfloat16* Bsm = smem + 6 * 128 * 24;     // [6][128][24]

    const int bx = blockIdx.x % ga.gx, by = blockIdx.x / ga.gx;
    const int bm = bx * 128, bn = by * 128;

    const int tid = threadIdx.x;
    const int w = tid >> 5, lane = tid & 31;
    const int wm = (w >> 1) * 32, wn = (w & 1) * 64;
    const int gid = lane >> 2, tig = lane & 3;
    float acc[2][8][4] = {};

    const unsigned asBase = (unsigned)__cvta_generic_to_shared(Asm);
    const unsigned bsBase = (unsigned)__cvta_generic_to_shared(Bsm);
    const unsigned aoffL = (unsigned)((wm + (lane & 15)) * 48 + (lane >> 4) * 16);
    const unsigned boffL = (unsigned)((wn + ((lane >> 4) << 3) + (lane & 7)) * 48
                                      + ((lane >> 3) & 1) * 16);
    const int srow = tid >> 1, sch = tid & 1;
    const bool aval = (bm + srow) < ga.M;
    const __nv_bfloat16* Agp = ga.A + (size_t)(bm + srow) * K + sch * 8;
    const __nv_bfloat16* Bgp = ga.Bt + (size_t)(bn + srow) * K + sch * 8;
    const unsigned daBase = asBase + (unsigned)(srow * 48 + sch * 16);
    const unsigned dbBase = bsBase + (unsigned)(srow * 48 + sch * 16);
    const int aSz = aval ? 16 : 0;

    auto issuePair = [&](int p) {
        int s0 = (2 * p) % 6;
        int k0 = p * 32;
        asm volatile("cp.async.ca.shared.global [%0], [%1], 16, %2;"
                     :: "r"(daBase + s0 * 6144), "l"(Agp + k0), "r"(aSz));
        asm volatile("cp.async.ca.shared.global [%0], [%1], 16, %2;"
                     :: "r"(daBase + (s0 + 1) * 6144), "l"(Agp + k0 + 16), "r"(aSz));
        asm volatile("cp.async.ca.shared.global [%0], [%1], 16;"
                     :: "r"(dbBase + s0 * 6144), "l"(Bgp + k0));
        asm volatile("cp.async.ca.shared.global [%0], [%1], 16;"
                     :: "r"(dbBase + (s0 + 1) * 6144), "l"(Bgp + k0 + 16));
        asm volatile("cp.async.commit_group;" ::: "memory");
    };

    const int TP = K >> 5;
    issuePair(0);
    issuePair(1);

    for (int p = 0; p < TP; p++) {
        asm volatile("cp.async.wait_group 1;" ::: "memory");
        __syncthreads();
#pragma unroll
        for (int sub = 0; sub < 2; sub++) {
            const int buf = (2 * p + sub) % 6;
            unsigned af[2][4], bfr[4][4];
            unsigned ab = asBase + (unsigned)(buf * 6144) + aoffL;
            ldsm4(af[0], ab);
            ldsm4(af[1], ab + 16 * 48);
            unsigned bb = bsBase + (unsigned)(buf * 6144) + boffL;
#pragma unroll
            for (int bt = 0; bt < 4; bt++) ldsm4(bfr[bt], bb + bt * 16 * 48);
#pragma unroll
            for (int mt = 0; mt < 2; mt++)
#pragma unroll
                for (int nt = 0; nt < 8; nt++)
                    mma16(acc[mt][nt], af[mt],
                          bfr[nt >> 1][(nt & 1) * 2], bfr[nt >> 1][(nt & 1) * 2 + 1]);
        }
        if (p + 2 < TP) issuePair(p + 2);
        else asm volatile("cp.async.commit_group;" ::: "memory");
    }

    // C write (bf16)
#pragma unroll
    for (int mt = 0; mt < 2; mt++) {
#pragma unroll
        for (int nt = 0; nt < 8; nt++) {
            int r0 = bm + wm + mt * 16 + gid;
            int c = bn + wn + nt * 8 + tig * 2;
            if (r0 < ga.M)
                *reinterpret_cast<unsigned*>(ga.C + (size_t)r0 * N + c) =
                    packbf(acc[mt][nt][0], acc[mt][nt][1]);
            if (r0 + 8 < ga.M)
                *reinterpret_cast<unsigned*>(ga.C + (size_t)(r0 + 8) * N + c) =
                    packbf(acc[mt][nt][2], acc[mt][nt][3]);
        }
    }

    // score epilogue (always two scores for node GEMMs); unique-writer stores
    {
        const int pidx = (PS == 4) ? ((bn + wn) >> 6) : 0;
        float wpv[8][2], wqv[8][2];
#pragma unroll
        for (int nt = 0; nt < 8; nt++) {
            int c = bn + wn + nt * 8 + tig * 2;
            wpv[nt][0] = ga.wp[c]; wpv[nt][1] = ga.wp[c + 1];
            wqv[nt][0] = ga.wq[c]; wqv[nt][1] = ga.wq[c + 1];
        }
#pragma unroll
        for (int mt = 0; mt < 2; mt++) {
#pragma unroll
            for (int half = 0; half < 2; half++) {
                float p = 0.f, q = 0.f;
#pragma unroll
                for (int nt = 0; nt < 8; nt++) {
                    p += acc[mt][nt][half * 2 + 0] * wpv[nt][0]
                       + acc[mt][nt][half * 2 + 1] * wpv[nt][1];
                    q += acc[mt][nt][half * 2 + 0] * wqv[nt][0]
                       + acc[mt][nt][half * 2 + 1] * wqv[nt][1];
                }
                p += __shfl_xor_sync(0xffffffffu, p, 1);
                p += __shfl_xor_sync(0xffffffffu, p, 2);
                q += __shfl_xor_sync(0xffffffffu, q, 1);
                q += __shfl_xor_sync(0xffffffffu, q, 2);
                int r = bm + wm + mt * 16 + gid + half * 8;
                if (tig == 0 && r < ga.M) {
                    ga.P[(size_t)r * PS + pidx] = p;
                    ga.Q[(size_t)r * PS + pidx] = q;
                }
            }
        }
    }
}

// ------- layer1 edge attention: warp per edge (raw copy only now) ----------------
__global__ __launch_bounds__(256)
void edge_attn1(const int* __restrict__ el, const float* __restrict__ a2) {
    int e = blockIdx.x * 8 + (threadIdx.x >> 5);
    if (e >= N_EDGES_C) return;
    int lane = threadIdx.x & 31;
    int h = lane >> 3, jl = lane & 7;
    float se = g_se1[e * 4 + h];
    int ids[MAX_ARITY];
    float s[MAX_ARITY];
#pragma unroll
    for (int ai = 0; ai < MAX_ARITY; ai++) ids[ai] = el[e * MAX_ARITY + ai];
#pragma unroll
    for (int ai = 0; ai < MAX_ARITY; ai++)
        s[ai] = (ids[ai] > 0) ? lreluf(se + g_pn1[(ids[ai] - 1) * 4 + h]) : -1e9f;
    float m = s[0];
#pragma unroll
    for (int ai = 1; ai < MAX_ARITY; ai++) m = fmaxf(m, s[ai]);
    float wv[MAX_ARITY], den = 0.f;
#pragma unroll
    for (int ai = 0; ai < MAX_ARITY; ai++) { wv[ai] = expf(s[ai] - m); den += wv[ai]; }
    float inv = 1.f / den;
    float o[8] = {};
#pragma unroll
    for (int ai = 0; ai < MAX_ARITY; ai++) {
        if (ids[ai] > 0) {
            uint4 u = *reinterpret_cast<const uint4*>(
                g_hn1 + (size_t)(ids[ai] - 1) * 256 + lane * 8);
            float f[8]; unpack8(u, f);
            float wg = wv[ai] * inv;
#pragma unroll
            for (int i = 0; i < 8; i++) o[i] += wg * f[i];
        }
    }
    *reinterpret_cast<uint4*>(g_eo1 + (size_t)e * 256 + lane * 8) = pack8(o);
    float pe = 0.f;
#pragma unroll
    for (int i = 0; i < 8; i++) pe += o[i] * a2[h * 128 + 64 + jl * 8 + i];
    pe = seg8_sum(pe);
    if (jl == 0) g_pe1[e * 4 + h] = pe;
}

// ------- layer1 node attention: warp per node, +ELU ------------------------------
__global__ __launch_bounds__(256)
void node_attn1(const int* __restrict__ nl) {
    int n = blockIdx.x * 8 + (threadIdx.x >> 5);
    if (n >= N_NODES_C) return;
    int lane = threadIdx.x & 31;
    int h = lane >> 3;
    float sn = g_sn1[n * 4 + h];
    int ids[MAX_DEG];
    float s[MAX_DEG];
#pragma unroll
    for (int di = 0; di < MAX_DEG; di++) ids[di] = nl[n * MAX_DEG + di];
#pragma unroll
    for (int di = 0; di < MAX_DEG; di++)
        s[di] = (ids[di] > 0) ? lreluf(sn + g_pe1[(ids[di] - 1) * 4 + h]) : -1e9f;
    float m = s[0];
#pragma unroll
    for (int di = 1; di < MAX_DEG; di++) m = fmaxf(m, s[di]);
    float wv[MAX_DEG], den = 0.f;
#pragma unroll
    for (int di = 0; di < MAX_DEG; di++) { wv[di] = expf(s[di] - m); den += wv[di]; }
    float inv = 1.f / den;
    float o[8] = {};
#pragma unroll
    for (int di = 0; di < MAX_DEG; di++) {
        if (ids[di] > 0) {
            uint4 u = *reinterpret_cast<const uint4*>(
                g_eo1 + (size_t)(ids[di] - 1) * 256 + lane * 8);
            float f[8]; unpack8(u, f);
            float wg = wv[di] * inv;
#pragma unroll
            for (int i = 0; i < 8; i++) o[i] += wg * f[i];
        }
    }
#pragma unroll
    for (int i = 0; i < 8; i++) o[i] = eluf(o[i]);
    *reinterpret_cast<uint4*>(g_no1 + (size_t)n * 256 + lane * 8) = pack8(o);
}

// ------- layer2 edge attention ----------------------------------------------------
__global__ __launch_bounds__(256)
void edge_attn2(const int* __restrict__ el, const float* __restrict__ a2o) {
    int e = blockIdx.x * 8 + (threadIdx.x >> 5);
    if (e >= N_EDGES_C) return;
    int lane = threadIdx.x & 31;
    float se = g_se2[e];
    int ids[MAX_ARITY];
    float s[MAX_ARITY];
#pragma unroll
    for (int ai = 0; ai < MAX_ARITY; ai++) ids[ai] = el[e * MAX_ARITY + ai];
#pragma unroll
    for (int ai = 0; ai < MAX_ARITY; ai++)
        s[ai] = (ids[ai] > 0) ? lreluf(se + g_pn2[ids[ai] - 1]) : -1e9f;
    float m = s[0];
#pragma unroll
    for (int ai = 1; ai < MAX_ARITY; ai++) m = fmaxf(m, s[ai]);
    float wv[MAX_ARITY], den = 0.f;
#pragma unroll
    for (int ai = 0; ai < MAX_ARITY; ai++) { wv[ai] = expf(s[ai] - m); den += wv[ai]; }
    float inv = 1.f / den;
    float o[4] = {};
#pragma unroll
    for (int ai = 0; ai < MAX_ARITY; ai++) {
        if (ids[ai] > 0) {
            uint2 u = *reinterpret_cast<const uint2*>(
                g_hn2 + (size_t)(ids[ai] - 1) * 128 + lane * 4);
            float2 x = unpackbf(u.x), y = unpackbf(u.y);
            float wg = wv[ai] * inv;
            o[0] += wg * x.x; o[1] += wg * x.y; o[2] += wg * y.x; o[3] += wg * y.y;
        }
    }
    *reinterpret_cast<float4*>(g_eo2 + (size_t)e * 128 + lane * 4) =
        make_float4(o[0], o[1], o[2], o[3]);
    float pe = 0.f;
#pragma unroll
    for (int i = 0; i < 4; i++) pe += o[i] * a2o[128 + lane * 4 + i];
    pe = warp_sum(pe);
    if (lane == 0) g_pe2[e] = pe;
}

// ------- layer2 node attention: pruned to batch-referenced -----------------------
__global__ __launch_bounds__(256)
void node_attn2(const int* __restrict__ nl) {
    int n = blockIdx.x * 8 + (threadIdx.x >> 5);
    if (n >= N_NODES_C) return;
    if (!g_mask[n]) return;
    int lane = threadIdx.x & 31;
    float sn = g_sn2[n];
    int ids[MAX_DEG];
    float s[MAX_DEG];
#pragma unroll
    for (int di = 0; di < MAX_DEG; di++) ids[di] = nl[n * MAX_DEG + di];
#pragma unroll
    for (int di = 0; di < MAX_DEG; di++)
        s[di] = (ids[di] > 0) ? lreluf(sn + g_pe2[ids[di] - 1]) : -1e9f;
    float m = s[0];
#pragma unroll
    for (int di = 1; di < MAX_DEG; di++) m = fmaxf(m, s[di]);
    float wv[MAX_DEG], den = 0.f;
#pragma unroll
    for (int di = 0; di < MAX_DEG; di++) { wv[di] = expf(s[di] - m); den += wv[di]; }
    float inv = 1.f / den;
    float o[4] = {};
#pragma unroll
    for (int di = 0; di < MAX_DEG; di++) {
        if (ids[di] > 0) {
            float4 x = *reinterpret_cast<const float4*>(
                g_eo2 + (size_t)(ids[di] - 1) * 128 + lane * 4);
            float wg = wv[di] * inv;
            o[0] += wg * x.x; o[1] += wg * x.y; o[2] += wg * x.z; o[3] += wg * x.w;
        }
    }
    *reinterpret_cast<float4*>(g_no2 + (size_t)n * 128 + lane * 4) =
        make_float4(o[0], o[1], o[2], o[3]);
}

// ---------------- final batch gather ----------------
__global__ __launch_bounds__(128)
void gather_out(const int* __restrict__ bi, float* __restrict__ out) {
    int b = blockIdx.x;
    int t = threadIdx.x;
    __shared__ int ids[7];
    __shared__ int lastnz;
    if (t < 7) ids[t] = bi[b * 7 + t];
    __syncthreads();
    if (t == 0) {
        int ln = 0;
#pragma unroll
        for (int j = 1; j < 7; j++) if (ids[j] != 0) ln = j;
        lastnz = ln;
    }
    __syncthreads();
    int ln = lastnz;
    out[(size_t)b * 896 + t] = eluf(g_eo2[(size_t)(ids[0] - 1) * 128 + t]);
#pragma unroll
    for (int a = 1; a < 7; a++) {
        int nid = ids[a] - 1;
        if (nid < 0) nid += N_NODES_C;
        float g = (a <= ln) ? eluf(g_no2[(size_t)nid * 128 + t]) : 1.0f;
        out[(size_t)b * 896 + a * 128 + t] = g;
    }
}

// ---------------- launch ----------------
extern "C" void kernel_launch(void* const* d_in, const int* in_sizes, int n_in,
                              void* d_out, int out_size) {
    (void)in_sizes; (void)n_in; (void)out_size;
    const int*   bi    = (const int*)d_in[0];
    const int*   el    = (const int*)d_in[1];
    const int*   nl    = (const int*)d_in[2];
    const float* nemb  = (const float*)d_in[3];
    const float* eemb  = (const float*)d_in[4];
    const float* Wn    = (const float*)d_in[5];
    const float* We    = (const float*)d_in[6];
    const float* a1    = (const float*)d_in[7];
    const float* a2    = (const float*)d_in[8];
    const float* Wn_o  = (const float*)d_in[9];
    const float* We_o  = (const float*)d_in[10];
    const float* a1_o  = (const float*)d_in[11];
    const float* a2_o  = (const float*)d_in[12];
    float* out = (float*)d_out;

    __nv_bfloat16 *embn, *hn1, *no1, *hn2, *bt1n, *bt2n;
    float *pn1, *sn1, *pn2, *sn2;
    float *wpn1, *wqn1, *wpn2, *wqn2;
    cudaGetSymbolAddress((void**)&embn, g_embn);
    cudaGetSymbolAddress((void**)&hn1, g_hn1);
    cudaGetSymbolAddress((void**)&no1, g_no1);
    cudaGetSymbolAddress((void**)&hn2, g_hn2);
    cudaGetSymbolAddress((void**)&pn1, g_pn1);
    cudaGetSymbolAddress((void**)&sn1, g_sn1);
    cudaGetSymbolAddress((void**)&pn2, g_pn2);
    cudaGetSymbolAddress((void**)&sn2, g_sn2);
    cudaGetSymbolAddress((void**)&wpn1, g_wpn1);
    cudaGetSymbolAddress((void**)&wqn1, g_wqn1);
    cudaGetSymbolAddress((void**)&wpn2, g_wpn2);
    cudaGetSymbolAddress((void**)&wqn2, g_wqn2);
    cudaGetSymbolAddress((void**)&bt1n, g_Bt1n);
    cudaGetSymbolAddress((void**)&bt2n, g_Bt2n);

    static bool attr_set = false;
    if (!attr_set) {
        cudaFuncSetAttribute(gemm_nd, cudaFuncAttributeMaxDynamicSharedMemorySize,
                             73728);
        attr_set = true;
    }

    prep<<<782, 256>>>(Wn, We, Wn_o, a1, a2, a1_o, a2_o, We_o);
    conv_emb<<<3125, 256>>>(nemb, eemb);
    mark_nodes<<<96, 256>>>(bi);

    // layer1: node projection GEMM (+fused pn1/sn1), edge scores via GEMV
    GArgs n1{embn, bt1n, hn1, N_NODES_C, wpn1, wqn1, pn1, sn1, 391};
    gemm_nd<<<782, 256, 73728>>>(n1, 256, 128, 4);
    gemv_se1<<<3125, 256>>>();

    edge_attn1<<<3125, 256>>>(el, a2);
    node_attn1<<<6250, 256>>>(nl);

    // layer2: node projection GEMM (+fused pn2/sn2), edge scores via GEMV
    GArgs n2{no1, bt2n, hn2, N_NODES_C, wpn2, wqn2, pn2, sn2, 391};
    gemm_nd<<<391, 256, 73728>>>(n2, 128, 256, 1);
    gemv_se2<<<3125, 256>>>();

    edge_attn2<<<3125, 256>>>(el, a1_o);
    node_attn2<<<6250, 256>>>(nl);

    gather_out<<<BATCH_C, 128>>>(bi, out);
}

// round 13
// speedup vs baseline: 1.0386x; 1.0386x over previous
#include <cuda_runtime.h>
#include <cuda_bf16.h>
#include <cstdint>

#define N_NODES_C 50000
#define N_EDGES_C 25000
#define MAX_ARITY 6
#define MAX_DEG 8
#define BATCH_C 4096

// ---------------- scratch (device globals; no allocations allowed) ----------------
__device__ __align__(256) __nv_bfloat16 g_embn[N_NODES_C * 128];
__device__ __align__(256) __nv_bfloat16 g_embe[N_EDGES_C * 128];
__device__ __align__(256) __nv_bfloat16 g_hn1[N_NODES_C * 256];
__device__ __align__(256) __nv_bfloat16 g_eo1[N_EDGES_C * 256];
__device__ __align__(256) __nv_bfloat16 g_no1[N_NODES_C * 256];
__device__ __align__(256) __nv_bfloat16 g_hn2[N_NODES_C * 128];
__device__ __align__(256) float g_eo2[N_EDGES_C * 128];
__device__ __align__(256) float g_no2[N_NODES_C * 128];
// pre-transposed bf16 weights, [n][k] (node projections only)
__device__ __align__(256) __nv_bfloat16 g_Bt1n[256 * 128];
__device__ __align__(256) __nv_bfloat16 g_Bt2n[128 * 256];
// score-weight vectors for node-GEMM epilogues
__device__ float g_wpn1[256];
__device__ float g_wqn1[256];
__device__ float g_wpn2[128];
__device__ float g_wqn2[128];
// collapsed edge-score GEMV vectors (fp32): v = B @ w
__device__ float g_vpe1[512];   // [h][k]: sum_j We[h][k][j]*a1[h][j]
__device__ float g_vpe2[256];   // [k]:    sum_j We_o[k][j]*a1_o[j]
// scalar score caches
__device__ float g_pn1[N_NODES_C * 4];
__device__ float g_sn1[N_NODES_C * 4];
__device__ float g_se1[N_EDGES_C * 4];
__device__ float g_pe1[N_EDGES_C * 4];
__device__ float g_pn2[N_NODES_C];
__device__ float g_sn2[N_NODES_C];
__device__ float g_se2[N_EDGES_C];
__device__ float g_pe2[N_EDGES_C];
__device__ unsigned char g_mask[N_NODES_C];

// ---------------- helpers ----------------
__device__ __forceinline__ float warp_sum(float v) {
#pragma unroll
    for (int o = 16; o > 0; o >>= 1) v += __shfl_xor_sync(0xffffffffu, v, o);
    return v;
}
__device__ __forceinline__ float seg8_sum(float v) {
#pragma unroll
    for (int o = 4; o > 0; o >>= 1) v += __shfl_xor_sync(0xffffffffu, v, o);
    return v;
}
__device__ __forceinline__ float eluf(float x)  { return x > 0.f ? x : expm1f(x); }
__device__ __forceinline__ float lreluf(float x){ return x > 0.f ? x : 0.2f * x; }

__device__ __forceinline__ void ldsm4(unsigned r[4], unsigned addr) {
    asm volatile("ldmatrix.sync.aligned.m8n8.x4.shared.b16 {%0,%1,%2,%3},[%4];"
                 : "=r"(r[0]), "=r"(r[1]), "=r"(r[2]), "=r"(r[3]) : "r"(addr));
}
__device__ __forceinline__ void mma16(float c[4], const unsigned a[4],
                                      unsigned b0, unsigned b1) {
    asm volatile(
        "mma.sync.aligned.m16n8k16.row.col.f32.bf16.bf16.f32 "
        "{%0,%1,%2,%3},{%4,%5,%6,%7},{%8,%9},{%0,%1,%2,%3};"
        : "+f"(c[0]), "+f"(c[1]), "+f"(c[2]), "+f"(c[3])
        : "r"(a[0]), "r"(a[1]), "r"(a[2]), "r"(a[3]), "r"(b0), "r"(b1));
}

__device__ __forceinline__ unsigned packbf(float a, float b) {
    __nv_bfloat162 h = __floats2bfloat162_rn(a, b);
    return *reinterpret_cast<unsigned*>(&h);
}
__device__ __forceinline__ float2 unpackbf(unsigned u) {
    return __bfloat1622float2(*reinterpret_cast<__nv_bfloat162*>(&u));
}
__device__ __forceinline__ void unpack8(uint4 u, float f[8]) {
    float2 a = unpackbf(u.x), b = unpackbf(u.y), c = unpackbf(u.z), d = unpackbf(u.w);
    f[0] = a.x; f[1] = a.y; f[2] = b.x; f[3] = b.y;
    f[4] = c.x; f[5] = c.y; f[6] = d.x; f[7] = d.y;
}
__device__ __forceinline__ uint4 pack8(const float f[8]) {
    uint4 u;
    u.x = packbf(f[0], f[1]); u.y = packbf(f[2], f[3]);
    u.z = packbf(f[4], f[5]); u.w = packbf(f[6], f[7]);
    return u;
}

// ---------------- prep ----------------
__global__ void prep(const float* __restrict__ Wn, const float* __restrict__ We,
                     const float* __restrict__ Wn_o, const float* __restrict__ We_o,
                     const float* __restrict__ a1, const float* __restrict__ a2,
                     const float* __restrict__ a1o, const float* __restrict__ a2o) {
    int i = blockIdx.x * 256 + threadIdx.x;
    if (i < 32768) {
        int c = i >> 7, k = i & 127;
        int h = c >> 6, j = c & 63;
        g_Bt1n[i] = __float2bfloat16_rn(Wn[h * 8192 + k * 64 + j]);
        int n2 = i >> 8, k2 = i & 255;
        g_Bt2n[i] = __float2bfloat16_rn(Wn_o[k2 * 128 + n2]);
    }
    if (i < 256) {
        int h = i >> 6, j = i & 63;
        g_wpn1[i] = a1[h * 128 + 64 + j];
        g_wqn1[i] = a2[h * 128 + j];
    }
    if (i < 128) {
        g_wpn2[i] = a1o[128 + i];
        g_wqn2[i] = a2o[i];
    }
    if (i < 512) {
        int h = i >> 7, k = i & 127;
        float s = 0.f;
#pragma unroll 8
        for (int j = 0; j < 64; j++) s += We[h * 8192 + k * 64 + j] * a1[h * 128 + j];
        g_vpe1[i] = s;
    }
    if (i < 256) {
        float s = 0.f;
#pragma unroll 8
        for (int j = 0; j < 128; j++) s += We_o[i * 128 + j] * a1o[j];
        g_vpe2[i] = s;
    }
    if (i < N_NODES_C) g_mask[i] = 0;
}

// ---------------- convert embeddings fp32 -> bf16 ----------------
__global__ void conv_emb(const float* __restrict__ nemb, const float* __restrict__ eemb) {
    int i = blockIdx.x * 256 + threadIdx.x;
    if (i < (N_NODES_C * 128) / 8) {
        float4 v0 = *reinterpret_cast<const float4*>(nemb + i * 8);
        float4 v1 = *reinterpret_cast<const float4*>(nemb + i * 8 + 4);
        uint4 u;
        u.x = packbf(v0.x, v0.y); u.y = packbf(v0.z, v0.w);
        u.z = packbf(v1.x, v1.y); u.w = packbf(v1.z, v1.w);
        *reinterpret_cast<uint4*>(g_embn + i * 8) = u;
    }
    if (i < (N_EDGES_C * 128) / 8) {
        float4 v0 = *reinterpret_cast<const float4*>(eemb + i * 8);
        float4 v1 = *reinterpret_cast<const float4*>(eemb + i * 8 + 4);
        uint4 u;
        u.x = packbf(v0.x, v0.y); u.y = packbf(v0.z, v0.w);
        u.z = packbf(v1.x, v1.y); u.w = packbf(v1.z, v1.w);
        *reinterpret_cast<uint4*>(g_embe + i * 8) = u;
    }
}

// ---------------- mark batch-referenced nodes ----------------
__global__ void mark_nodes(const int* __restrict__ bi) {
    int i = blockIdx.x * 256 + threadIdx.x;
    if (i >= BATCH_C * 6) return;
    int b = i / 6, a = i % 6 + 1;
    int nid = bi[b * 7 + a] - 1;
    if (nid < 0) nid += N_NODES_C;
    g_mask[nid] = 1;
}

// ---------------- fused GEMM + GEMV launch -----------------------------------------
// blocks < split: node-projection GEMM (BM=128, BN=128, 6-stage cp.async, fused
// pn/sn epilogue, unique-writer stores). blocks >= split: edge-score GEMV.
struct GArgs {
    const __nv_bfloat16* A;
    const __nv_bfloat16* Bt;
    __nv_bfloat16* C;
    int M;
    const float* wp;
    const float* wq;
    float* P;
    float* Q;
    int gx;       // blocks in x
};
struct GvArgs {
    const __nv_bfloat16* E;   // edge features, row-major
    int M;                    // #edges
    const float* v;           // GEMV vector(s)
    float* S;                 // output scores
    int mode;                 // 1: 4 heads, width 128; 2: 1 head, width 256, ELU
};

__global__ __launch_bounds__(256, 2)
void gemm_gv(GArgs ga, GvArgs gv, int split, int N, int K, int PS) {
    extern __shared__ __align__(16) __nv_bfloat16 smem[];
    const int tid = threadIdx.x;
    const int lane = tid & 31;

    if ((int)blockIdx.x >= split) {
        // ----------------- GEMV segment: warp x 8 edges -----------------
        const int gwid = ((int)blockIdx.x - split) * 8 + (tid >> 5);
        if (gv.mode == 1) {
            float v[4][4];
#pragma unroll
            for (int h = 0; h < 4; h++)
#pragma unroll
                for (int i = 0; i < 4; i++) v[h][i] = gv.v[h * 128 + lane * 4 + i];
#pragma unroll
            for (int t = 0; t < 8; t++) {
                int e = gwid * 8 + t;
                if (e >= gv.M) break;
                uint2 u = *reinterpret_cast<const uint2*>(
                    gv.E + (size_t)e * 128 + lane * 4);
                float2 x = unpackbf(u.x), y = unpackbf(u.y);
                float f[4] = {x.x, x.y, y.x, y.y};
                float p[4];
#pragma unroll
                for (int h = 0; h < 4; h++) {
                    float s = f[0] * v[h][0] + f[1] * v[h][1]
                            + f[2] * v[h][2] + f[3] * v[h][3];
                    p[h] = warp_sum(s);
                }
                if (lane == 0)
                    *reinterpret_cast<float4*>(gv.S + e * 4) =
                        make_float4(p[0], p[1], p[2], p[3]);
            }
        } else {
            float v[8];
#pragma unroll
            for (int i = 0; i < 8; i++) v[i] = gv.v[lane * 8 + i];
#pragma unroll
            for (int t = 0; t < 8; t++) {
                int e = gwid * 8 + t;
                if (e >= gv.M) break;
                uint4 u = *reinterpret_cast<const uint4*>(
                    gv.E + (size_t)e * 256 + lane * 8);
                float f[8]; unpack8(u, f);
                float s = 0.f;
#pragma unroll
                for (int i = 0; i < 8; i++) s += eluf(f[i]) * v[i];
                s = warp_sum(s);
                if (lane == 0) gv.S[e] = s;
            }
        }
        return;
    }

    // ----------------- GEMM segment -----------------
    __nv_bfloat16* Asm = smem;                    // [6][128][24]
    __nv_bfloat16* Bsm = smem + 6 * 128 * 24;     // [6][128][24]
    const int bx = (int)blockIdx.x % ga.gx, by = (int)blockIdx.x / ga.gx;
    const int bm = bx * 128, bn = by * 128;
    const int w = tid >> 5;
    const int wm = (w >> 1) * 32, wn = (w & 1) * 64;
    const int gid = lane >> 2, tig = lane & 3;
    float acc[2][8][4] = {};

    const unsigned asBase = (unsigned)__cvta_generic_to_shared(Asm);
    const unsigned bsBase = (unsigned)__cvta_generic_to_shared(Bsm);
    const unsigned aoffL = (unsigned)((wm + (lane & 15)) * 48 + (lane >> 4) * 16);
    const unsigned boffL = (unsigned)((wn + ((lane >> 4) << 3) + (lane & 7)) * 48
                                      + ((lane >> 3) & 1) * 16);
    const int srow = tid >> 1, sch = tid & 1;
    const bool aval = (bm + srow) < ga.M;
    const __nv_bfloat16* Agp = ga.A + (size_t)(bm + srow) * K + sch * 8;
    const __nv_bfloat16* Bgp = ga.Bt + (size_t)(bn + srow) * K + sch * 8;
    const unsigned daBase = asBase + (unsigned)(srow * 48 + sch * 16);
    const unsigned dbBase = bsBase + (unsigned)(srow * 48 + sch * 16);
    const int aSz = aval ? 16 : 0;

    auto issuePair = [&](int p) {
        int s0 = (2 * p) % 6;
        int k0 = p * 32;
        asm volatile("cp.async.ca.shared.global [%0], [%1], 16, %2;"
                     :: "r"(daBase + s0 * 6144), "l"(Agp + k0), "r"(aSz));
        asm volatile("cp.async.ca.shared.global [%0], [%1], 16, %2;"
                     :: "r"(daBase + (s0 + 1) * 6144), "l"(Agp + k0 + 16), "r"(aSz));
        asm volatile("cp.async.ca.shared.global [%0], [%1], 16;"
                     :: "r"(dbBase + s0 * 6144), "l"(Bgp + k0));
        asm volatile("cp.async.ca.shared.global [%0], [%1], 16;"
                     :: "r"(dbBase + (s0 + 1) * 6144), "l"(Bgp + k0 + 16));
        asm volatile("cp.async.commit_group;" ::: "memory");
    };

    const int TP = K >> 5;
    issuePair(0);
    issuePair(1);

    for (int p = 0; p < TP; p++) {
        asm volatile("cp.async.wait_group 1;" ::: "memory");
        __syncthreads();
#pragma unroll
        for (int sub = 0; sub < 2; sub++) {
            const int buf = (2 * p + sub) % 6;
            unsigned af[2][4], bfr[4][4];
            unsigned ab = asBase + (unsigned)(buf * 6144) + aoffL;
            ldsm4(af[0], ab);
            ldsm4(af[1], ab + 16 * 48);
            unsigned bb = bsBase + (unsigned)(buf * 6144) + boffL;
#pragma unroll
            for (int bt = 0; bt < 4; bt++) ldsm4(bfr[bt], bb + bt * 16 * 48);
#pragma unroll
            for (int mt = 0; mt < 2; mt++)
#pragma unroll
                for (int nt = 0; nt < 8; nt++)
                    mma16(acc[mt][nt], af[mt],
                          bfr[nt >> 1][(nt & 1) * 2], bfr[nt >> 1][(nt & 1) * 2 + 1]);
        }
        if (p + 2 < TP) issuePair(p + 2);
        else asm volatile("cp.async.commit_group;" ::: "memory");
    }

    // C write (bf16)
#pragma unroll
    for (int mt = 0; mt < 2; mt++) {
#pragma unroll
        for (int nt = 0; nt < 8; nt++) {
            int r0 = bm + wm + mt * 16 + gid;
            int c = bn + wn + nt * 8 + tig * 2;
            if (r0 < ga.M)
                *reinterpret_cast<unsigned*>(ga.C + (size_t)r0 * N + c) =
                    packbf(acc[mt][nt][0], acc[mt][nt][1]);
            if (r0 + 8 < ga.M)
                *reinterpret_cast<unsigned*>(ga.C + (size_t)(r0 + 8) * N + c) =
                    packbf(acc[mt][nt][2], acc[mt][nt][3]);
        }
    }

    // fused score epilogue (two scores; unique-writer stores)
    {
        const int pidx = (PS == 4) ? ((bn + wn) >> 6) : 0;
        float wpv[8][2], wqv[8][2];
#pragma unroll
        for (int nt = 0; nt < 8; nt++) {
            int c = bn + wn + nt * 8 + tig * 2;
            wpv[nt][0] = ga.wp[c]; wpv[nt][1] = ga.wp[c + 1];
            wqv[nt][0] = ga.wq[c]; wqv[nt][1] = ga.wq[c + 1];
        }
#pragma unroll
        for (int mt = 0; mt < 2; mt++) {
#pragma unroll
            for (int half = 0; half < 2; half++) {
                float p = 0.f, q = 0.f;
#pragma unroll
                for (int nt = 0; nt < 8; nt++) {
                    p += acc[mt][nt][half * 2 + 0] * wpv[nt][0]
                       + acc[mt][nt][half * 2 + 1] * wpv[nt][1];
                    q += acc[mt][nt][half * 2 + 0] * wqv[nt][0]
                       + acc[mt][nt][half * 2 + 1] * wqv[nt][1];
                }
                p += __shfl_xor_sync(0xffffffffu, p, 1);
                p += __shfl_xor_sync(0xffffffffu, p, 2);
                q += __shfl_xor_sync(0xffffffffu, q, 1);
                q += __shfl_xor_sync(0xffffffffu, q, 2);
                int r = bm + wm + mt * 16 + gid + half * 8;
                if (tig == 0 && r < ga.M) {
                    ga.P[(size_t)r * PS + pidx] = p;
                    ga.Q[(size_t)r * PS + pidx] = q;
                }
            }
        }
    }
}

// ------- layer1 edge attention: warp per edge (raw copy only) --------------------
__global__ __launch_bounds__(256)
void edge_attn1(const int* __restrict__ el, const float* __restrict__ a2) {
    int e = blockIdx.x * 8 + (threadIdx.x >> 5);
    if (e >= N_EDGES_C) return;
    int lane = threadIdx.x & 31;
    int h = lane >> 3, jl = lane & 7;
    float se = g_se1[e * 4 + h];
    int ids[MAX_ARITY];
    float s[MAX_ARITY];
#pragma unroll
    for (int ai = 0; ai < MAX_ARITY; ai++) ids[ai] = el[e * MAX_ARITY + ai];
#pragma unroll
    for (int ai = 0; ai < MAX_ARITY; ai++)
        s[ai] = (ids[ai] > 0) ? lreluf(se + g_pn1[(ids[ai] - 1) * 4 + h]) : -1e9f;
    float m = s[0];
#pragma unroll
    for (int ai = 1; ai < MAX_ARITY; ai++) m = fmaxf(m, s[ai]);
    float wv[MAX_ARITY], den = 0.f;
#pragma unroll
    for (int ai = 0; ai < MAX_ARITY; ai++) { wv[ai] = expf(s[ai] - m); den += wv[ai]; }
    float inv = 1.f / den;
    float o[8] = {};
#pragma unroll
    for (int ai = 0; ai < MAX_ARITY; ai++) {
        if (ids[ai] > 0) {
            uint4 u = *reinterpret_cast<const uint4*>(
                g_hn1 + (size_t)(ids[ai] - 1) * 256 + lane * 8);
            float f[8]; unpack8(u, f);
            float wg = wv[ai] * inv;
#pragma unroll
            for (int i = 0; i < 8; i++) o[i] += wg * f[i];
        }
    }
    *reinterpret_cast<uint4*>(g_eo1 + (size_t)e * 256 + lane * 8) = pack8(o);
    float pe = 0.f;
#pragma unroll
    for (int i = 0; i < 8; i++) pe += o[i] * a2[h * 128 + 64 + jl * 8 + i];
    pe = seg8_sum(pe);
    if (jl == 0) g_pe1[e * 4 + h] = pe;
}

// ------- layer1 node attention: warp per node, +ELU ------------------------------
__global__ __launch_bounds__(256)
void node_attn1(const int* __restrict__ nl) {
    int n = blockIdx.x * 8 + (threadIdx.x >> 5);
    if (n >= N_NODES_C) return;
    int lane = threadIdx.x & 31;
    int h = lane >> 3;
    float sn = g_sn1[n * 4 + h];
    int ids[MAX_DEG];
    float s[MAX_DEG];
#pragma unroll
    for (int di = 0; di < MAX_DEG; di++) ids[di] = nl[n * MAX_DEG + di];
#pragma unroll
    for (int di = 0; di < MAX_DEG; di++)
        s[di] = (ids[di] > 0) ? lreluf(sn + g_pe1[(ids[di] - 1) * 4 + h]) : -1e9f;
    float m = s[0];
#pragma unroll
    for (int di = 1; di < MAX_DEG; di++) m = fmaxf(m, s[di]);
    float wv[MAX_DEG], den = 0.f;
#pragma unroll
    for (int di = 0; di < MAX_DEG; di++) { wv[di] = expf(s[di] - m); den += wv[di]; }
    float inv = 1.f / den;
    float o[8] = {};
#pragma unroll
    for (int di = 0; di < MAX_DEG; di++) {
        if (ids[di] > 0) {
            uint4 u = *reinterpret_cast<const uint4*>(
                g_eo1 + (size_t)(ids[di] - 1) * 256 + lane * 8);
            float f[8]; unpack8(u, f);
            float wg = wv[di] * inv;
#pragma unroll
            for (int i = 0; i < 8; i++) o[i] += wg * f[i];
        }
    }
#pragma unroll
    for (int i = 0; i < 8; i++) o[i] = eluf(o[i]);
    *reinterpret_cast<uint4*>(g_no1 + (size_t)n * 256 + lane * 8) = pack8(o);
}

// ------- layer2 edge attention ----------------------------------------------------
__global__ __launch_bounds__(256)
void edge_attn2(const int* __restrict__ el, const float* __restrict__ a2o) {
    int e = blockIdx.x * 8 + (threadIdx.x >> 5);
    if (e >= N_EDGES_C) return;
    int lane = threadIdx.x & 31;
    float se = g_se2[e];
    int ids[MAX_ARITY];
    float s[MAX_ARITY];
#pragma unroll
    for (int ai = 0; ai < MAX_ARITY; ai++) ids[ai] = el[e * MAX_ARITY + ai];
#pragma unroll
    for (int ai = 0; ai < MAX_ARITY; ai++)
        s[ai] = (ids[ai] > 0) ? lreluf(se + g_pn2[ids[ai] - 1]) : -1e9f;
    float m = s[0];
#pragma unroll
    for (int ai = 1; ai < MAX_ARITY; ai++) m = fmaxf(m, s[ai]);
    float wv[MAX_ARITY], den = 0.f;
#pragma unroll
    for (int ai = 0; ai < MAX_ARITY; ai++) { wv[ai] = expf(s[ai] - m); den += wv[ai]; }
    float inv = 1.f / den;
    float o[4] = {};
#pragma unroll
    for (int ai = 0; ai < MAX_ARITY; ai++) {
        if (ids[ai] > 0) {
            uint2 u = *reinterpret_cast<const uint2*>(
                g_hn2 + (size_t)(ids[ai] - 1) * 128 + lane * 4);
            float2 x = unpackbf(u.x), y = unpackbf(u.y);
            float wg = wv[ai] * inv;
            o[0] += wg * x.x; o[1] += wg * x.y; o[2] += wg * y.x; o[3] += wg * y.y;
        }
    }
    *reinterpret_cast<float4*>(g_eo2 + (size_t)e * 128 + lane * 4) =
        make_float4(o[0], o[1], o[2], o[3]);
    float pe = 0.f;
#pragma unroll
    for (int i = 0; i < 4; i++) pe += o[i] * a2o[128 + lane * 4 + i];
    pe = warp_sum(pe);
    if (lane == 0) g_pe2[e] = pe;
}

// ------- layer2 node attention: pruned to batch-referenced -----------------------
__global__ __launch_bounds__(256)
void node_attn2(const int* __restrict__ nl) {
    int n = blockIdx.x * 8 + (threadIdx.x >> 5);
    if (n >= N_NODES_C) return;
    if (!g_mask[n]) return;
    int lane = threadIdx.x & 31;
    float sn = g_sn2[n];
    int ids[MAX_DEG];
    float s[MAX_DEG];
#pragma unroll
    for (int di = 0; di < MAX_DEG; di++) ids[di] = nl[n * MAX_DEG + di];
#pragma unroll
    for (int di = 0; di < MAX_DEG; di++)
        s[di] = (ids[di] > 0) ? lreluf(sn + g_pe2[ids[di] - 1]) : -1e9f;
    float m = s[0];
#pragma unroll
    for (int di = 1; di < MAX_DEG; di++) m = fmaxf(m, s[di]);
    float wv[MAX_DEG], den = 0.f;
#pragma unroll
    for (int di = 0; di < MAX_DEG; di++) { wv[di] = expf(s[di] - m); den += wv[di]; }
    float inv = 1.f / den;
    float o[4] = {};
#pragma unroll
    for (int di = 0; di < MAX_DEG; di++) {
        if (ids[di] > 0) {
            float4 x = *reinterpret_cast<const float4*>(
                g_eo2 + (size_t)(ids[di] - 1) * 128 + lane * 4);
            float wg = wv[di] * inv;
            o[0] += wg * x.x; o[1] += wg * x.y; o[2] += wg * x.z; o[3] += wg * x.w;
        }
    }
    *reinterpret_cast<float4*>(g_no2 + (size_t)n * 128 + lane * 4) =
        make_float4(o[0], o[1], o[2], o[3]);
}

// ---------------- final batch gather ----------------
__global__ __launch_bounds__(128)
void gather_out(const int* __restrict__ bi, float* __restrict__ out) {
    int b = blockIdx.x;
    int t = threadIdx.x;
    __shared__ int ids[7];
    __shared__ int lastnz;
    if (t < 7) ids[t] = bi[b * 7 + t];
    __syncthreads();
    if (t == 0) {
        int ln = 0;
#pragma unroll
        for (int j = 1; j < 7; j++) if (ids[j] != 0) ln = j;
        lastnz = ln;
    }
    __syncthreads();
    int ln = lastnz;
    out[(size_t)b * 896 + t] = eluf(g_eo2[(size_t)(ids[0] - 1) * 128 + t]);
#pragma unroll
    for (int a = 1; a < 7; a++) {
        int nid = ids[a] - 1;
        if (nid < 0) nid += N_NODES_C;
        float g = (a <= ln) ? eluf(g_no2[(size_t)nid * 128 + t]) : 1.0f;
        out[(size_t)b * 896 + a * 128 + t] = g;
    }
}

// ---------------- launch ----------------
extern "C" void kernel_launch(void* const* d_in, const int* in_sizes, int n_in,
                              void* d_out, int out_size) {
    (void)in_sizes; (void)n_in; (void)out_size;
    const int*   bi    = (const int*)d_in[0];
    const int*   el    = (const int*)d_in[1];
    const int*   nl    = (const int*)d_in[2];
    const float* nemb  = (const float*)d_in[3];
    const float* eemb  = (const float*)d_in[4];
    const float* Wn    = (const float*)d_in[5];
    const float* We    = (const float*)d_in[6];
    const float* a1    = (const float*)d_in[7];
    const float* a2    = (const float*)d_in[8];
    const float* Wn_o  = (const float*)d_in[9];
    const float* We_o  = (const float*)d_in[10];
    const float* a1_o  = (const float*)d_in[11];
    const float* a2_o  = (const float*)d_in[12];
    float* out = (float*)d_out;

    __nv_bfloat16 *embn, *embe, *hn1, *eo1, *no1, *hn2, *bt1n, *bt2n;
    float *pn1, *sn1, *se1, *pn2, *sn2, *se2;
    float *wpn1, *wqn1, *wpn2, *wqn2, *vpe1, *vpe2;
    cudaGetSymbolAddress((void**)&embn, g_embn);
    cudaGetSymbolAddress((void**)&embe, g_embe);
    cudaGetSymbolAddress((void**)&hn1, g_hn1);
    cudaGetSymbolAddress((void**)&eo1, g_eo1);
    cudaGetSymbolAddress((void**)&no1, g_no1);
    cudaGetSymbolAddress((void**)&hn2, g_hn2);
    cudaGetSymbolAddress((void**)&pn1, g_pn1);
    cudaGetSymbolAddress((void**)&sn1, g_sn1);
    cudaGetSymbolAddress((void**)&se1, g_se1);
    cudaGetSymbolAddress((void**)&pn2, g_pn2);
    cudaGetSymbolAddress((void**)&sn2, g_sn2);
    cudaGetSymbolAddress((void**)&se2, g_se2);
    cudaGetSymbolAddress((void**)&wpn1, g_wpn1);
    cudaGetSymbolAddress((void**)&wqn1, g_wqn1);
    cudaGetSymbolAddress((void**)&wpn2, g_wpn2);
    cudaGetSymbolAddress((void**)&wqn2, g_wqn2);
    cudaGetSymbolAddress((void**)&vpe1, g_vpe1);
    cudaGetSymbolAddress((void**)&vpe2, g_vpe2);
    cudaGetSymbolAddress((void**)&bt1n, g_Bt1n);
    cudaGetSymbolAddress((void**)&bt2n, g_Bt2n);

    static bool attr_set = false;
    if (!attr_set) {
        cudaFuncSetAttribute(gemm_gv, cudaFuncAttributeMaxDynamicSharedMemorySize,
                             73728);
        attr_set = true;
    }

    prep<<<782, 256>>>(Wn, We, Wn_o, We_o, a1, a2, a1_o, a2_o);
    conv_emb<<<3125, 256>>>(nemb, eemb);
    mark_nodes<<<96, 256>>>(bi);

    // ---- layer1: node GEMM (782 blocks) + se1 GEMV (391 blocks), one launch ----
    GArgs n1{embn, bt1n, hn1, N_NODES_C, wpn1, wqn1, pn1, sn1, 391};
    GvArgs v1{embe, N_EDGES_C, vpe1, se1, 1};
    gemm_gv<<<782 + 391, 256, 73728>>>(n1, v1, 782, 256, 128, 4);

    edge_attn1<<<3125, 256>>>(el, a2);
    node_attn1<<<6250, 256>>>(nl);

    // ---- layer2: node GEMM (391 blocks) + se2 GEMV (391 blocks), one launch ----
    GArgs n2{no1, bt2n, hn2, N_NODES_C, wpn2, wqn2, pn2, sn2, 391};
    GvArgs v2{eo1, N_EDGES_C, vpe2, se2, 2};
    gemm_gv<<<391 + 391, 256, 73728>>>(n2, v2, 391, 128, 256, 1);

    edge_attn2<<<3125, 256>>>(el, a1_o);
    node_attn2<<<6250, 256>>>(nl);

    gather_out<<<BATCH_C, 128>>>(bi, out);
}

// round 14
// speedup vs baseline: 1.0882x; 1.0478x over previous
#include <cuda_runtime.h>
#include <cuda_bf16.h>
#include <cstdint>

#define N_NODES_C 50000
#define N_EDGES_C 25000
#define MAX_ARITY 6
#define MAX_DEG 8
#define BATCH_C 4096

// ---------------- scratch (device globals; no allocations allowed) ----------------
__device__ __align__(256) __nv_bfloat16 g_embn[N_NODES_C * 128];
__device__ __align__(256) __nv_bfloat16 g_embe[N_EDGES_C * 128];
__device__ __align__(256) __nv_bfloat16 g_hn1[N_NODES_C * 256];
__device__ __align__(256) __nv_bfloat16 g_eo1[N_EDGES_C * 256];
__device__ __align__(256) __nv_bfloat16 g_no1[N_NODES_C * 256];
__device__ __align__(256) __nv_bfloat16 g_hn2[N_NODES_C * 128];
__device__ __align__(256) float g_eo2[N_EDGES_C * 128];
__device__ __align__(256) float g_no2[N_NODES_C * 128];
// pre-transposed bf16 weights, [n][k] (node projections only)
__device__ __align__(256) __nv_bfloat16 g_Bt1n[256 * 128];
__device__ __align__(256) __nv_bfloat16 g_Bt2n[128 * 256];
// score-weight vectors for node-GEMM epilogues
__device__ float g_wpn1[256];
__device__ float g_wqn1[256];
__device__ float g_wpn2[128];
__device__ float g_wqn2[128];
// collapsed edge-score GEMV vectors (fp32): v = B @ w
__device__ float g_vpe1[512];   // [h][k]: sum_j We[h][k][j]*a1[h][j]
__device__ float g_vpe2[256];   // [k]:    sum_j We_o[k][j]*a1_o[j]
// scalar score caches (all unique-writer; no zeroing needed)
__device__ float g_pn1[N_NODES_C * 4];
__device__ float g_sn1[N_NODES_C * 4];
__device__ float g_se1[N_EDGES_C * 4];
__device__ float g_pe1[N_EDGES_C * 4];
__device__ float g_pn2[N_NODES_C];
__device__ float g_sn2[N_NODES_C];
__device__ float g_se2[N_EDGES_C];
__device__ float g_pe2[N_EDGES_C];
__device__ unsigned char g_mask[N_NODES_C];

// ---------------- helpers ----------------
__device__ __forceinline__ float warp_sum(float v) {
#pragma unroll
    for (int o = 16; o > 0; o >>= 1) v += __shfl_xor_sync(0xffffffffu, v, o);
    return v;
}
__device__ __forceinline__ float seg8_sum(float v) {
#pragma unroll
    for (int o = 4; o > 0; o >>= 1) v += __shfl_xor_sync(0xffffffffu, v, o);
    return v;
}
__device__ __forceinline__ float eluf(float x)  { return x > 0.f ? x : expm1f(x); }
__device__ __forceinline__ float lreluf(float x){ return x > 0.f ? x : 0.2f * x; }

__device__ __forceinline__ void ldsm4(unsigned r[4], unsigned addr) {
    asm volatile("ldmatrix.sync.aligned.m8n8.x4.shared.b16 {%0,%1,%2,%3},[%4];"
                 : "=r"(r[0]), "=r"(r[1]), "=r"(r[2]), "=r"(r[3]) : "r"(addr));
}
__device__ __forceinline__ void mma16(float c[4], const unsigned a[4],
                                      unsigned b0, unsigned b1) {
    asm volatile(
        "mma.sync.aligned.m16n8k16.row.col.f32.bf16.bf16.f32 "
        "{%0,%1,%2,%3},{%4,%5,%6,%7},{%8,%9},{%0,%1,%2,%3};"
        : "+f"(c[0]), "+f"(c[1]), "+f"(c[2]), "+f"(c[3])
        : "r"(a[0]), "r"(a[1]), "r"(a[2]), "r"(a[3]), "r"(b0), "r"(b1));
}

__device__ __forceinline__ unsigned packbf(float a, float b) {
    __nv_bfloat162 h = __floats2bfloat162_rn(a, b);
    return *reinterpret_cast<unsigned*>(&h);
}
__device__ __forceinline__ float2 unpackbf(unsigned u) {
    return __bfloat1622float2(*reinterpret_cast<__nv_bfloat162*>(&u));
}
__device__ __forceinline__ void unpack8(uint4 u, float f[8]) {
    float2 a = unpackbf(u.x), b = unpackbf(u.y), c = unpackbf(u.z), d = unpackbf(u.w);
    f[0] = a.x; f[1] = a.y; f[2] = b.x; f[3] = b.y;
    f[4] = c.x; f[5] = c.y; f[6] = d.x; f[7] = d.y;
}
__device__ __forceinline__ uint4 pack8(const float f[8]) {
    uint4 u;
    u.x = packbf(f[0], f[1]); u.y = packbf(f[2], f[3]);
    u.z = packbf(f[4], f[5]); u.w = packbf(f[6], f[7]);
    return u;
}

// ---------------- prep: weights, score vectors, mask zero, emb conversion --------
__global__ void prep(const float* __restrict__ Wn, const float* __restrict__ We,
                     const float* __restrict__ Wn_o, const float* __restrict__ We_o,
                     const float* __restrict__ a1, const float* __restrict__ a2,
                     const float* __restrict__ a1o, const float* __restrict__ a2o,
                     const float* __restrict__ nemb, const float* __restrict__ eemb) {
    int i = blockIdx.x * 256 + threadIdx.x;
    // embedding conversion (8 floats -> 8 bf16 per thread)
    if (i < (N_NODES_C * 128) / 8) {
        float4 v0 = *reinterpret_cast<const float4*>(nemb + i * 8);
        float4 v1 = *reinterpret_cast<const float4*>(nemb + i * 8 + 4);
        uint4 u;
        u.x = packbf(v0.x, v0.y); u.y = packbf(v0.z, v0.w);
        u.z = packbf(v1.x, v1.y); u.w = packbf(v1.z, v1.w);
        *reinterpret_cast<uint4*>(g_embn + i * 8) = u;
    }
    if (i < (N_EDGES_C * 128) / 8) {
        float4 v0 = *reinterpret_cast<const float4*>(eemb + i * 8);
        float4 v1 = *reinterpret_cast<const float4*>(eemb + i * 8 + 4);
        uint4 u;
        u.x = packbf(v0.x, v0.y); u.y = packbf(v0.z, v0.w);
        u.z = packbf(v1.x, v1.y); u.w = packbf(v1.z, v1.w);
        *reinterpret_cast<uint4*>(g_embe + i * 8) = u;
    }
    if (i < 32768) {
        int c = i >> 7, k = i & 127;
        int h = c >> 6, j = c & 63;
        g_Bt1n[i] = __float2bfloat16_rn(Wn[h * 8192 + k * 64 + j]);
        int n2 = i >> 8, k2 = i & 255;
        g_Bt2n[i] = __float2bfloat16_rn(Wn_o[k2 * 128 + n2]);
    }
    if (i < 256) {
        int h = i >> 6, j = i & 63;
        g_wpn1[i] = a1[h * 128 + 64 + j];
        g_wqn1[i] = a2[h * 128 + j];
    }
    if (i < 128) {
        g_wpn2[i] = a1o[128 + i];
        g_wqn2[i] = a2o[i];
    }
    if (i < 512) {
        int h = i >> 7, k = i & 127;
        float s = 0.f;
#pragma unroll 8
        for (int j = 0; j < 64; j++) s += We[h * 8192 + k * 64 + j] * a1[h * 128 + j];
        g_vpe1[i] = s;
    }
    if (i < 256) {
        float s = 0.f;
#pragma unroll 8
        for (int j = 0; j < 128; j++) s += We_o[i * 128 + j] * a1o[j];
        g_vpe2[i] = s;
    }
    if (i < N_NODES_C) g_mask[i] = 0;
}

// ---------------- mark batch-referenced nodes ----------------
__global__ void mark_nodes(const int* __restrict__ bi) {
    int i = blockIdx.x * 256 + threadIdx.x;
    if (i >= BATCH_C * 6) return;
    int b = i / 6, a = i % 6 + 1;
    int nid = bi[b * 7 + a] - 1;
    if (nid < 0) nid += N_NODES_C;
    g_mask[nid] = 1;
}

// ---------------- fused GEMM + GEMV launch -----------------------------------------
struct GArgs {
    const __nv_bfloat16* A;
    const __nv_bfloat16* Bt;
    __nv_bfloat16* C;
    int M;
    const float* wp;
    const float* wq;
    float* P;
    float* Q;
    int gx;
};
struct GvArgs {
    const __nv_bfloat16* E;   // edge features [M][128]
    int M;
    const float* v;           // 4 x 128 vectors
    float* S;                 // [M][4]
};

__global__ __launch_bounds__(256, 2)
void gemm_gv(GArgs ga, GvArgs gv, int split, int N, int K, int PS) {
    extern __shared__ __align__(16) __nv_bfloat16 smem[];
    const int tid = threadIdx.x;
    const int lane = tid & 31;

    if ((int)blockIdx.x >= split) {
        // GEMV segment: se1[e,h] = embe[e,:] . vpe1[h,:], warp x 8 edges
        const int gwid = ((int)blockIdx.x - split) * 8 + (tid >> 5);
        float v[4][4];
#pragma unroll
        for (int h = 0; h < 4; h++)
#pragma unroll
            for (int i = 0; i < 4; i++) v[h][i] = gv.v[h * 128 + lane * 4 + i];
#pragma unroll
        for (int t = 0; t < 8; t++) {
            int e = gwid * 8 + t;
            if (e >= gv.M) break;
            uint2 u = *reinterpret_cast<const uint2*>(gv.E + (size_t)e * 128 + lane * 4);
            float2 x = unpackbf(u.x), y = unpackbf(u.y);
            float f[4] = {x.x, x.y, y.x, y.y};
            float p[4];
#pragma unroll
            for (int h = 0; h < 4; h++) {
                float s = f[0] * v[h][0] + f[1] * v[h][1]
                        + f[2] * v[h][2] + f[3] * v[h][3];
                p[h] = warp_sum(s);
            }
            if (lane == 0)
                *reinterpret_cast<float4*>(gv.S + e * 4) =
                    make_float4(p[0], p[1], p[2], p[3]);
        }
        return;
    }

    // GEMM segment
    __nv_bfloat16* Asm = smem;                    // [6][128][24]
    __nv_bfloat16* Bsm = smem + 6 * 128 * 24;     // [6][128][24]
    const int bx = (int)blockIdx.x % ga.gx, by = (int)blockIdx.x / ga.gx;
    const int bm = bx * 128, bn = by * 128;
    const int w = tid >> 5;
    const int wm = (w >> 1) * 32, wn = (w & 1) * 64;
    const int gid = lane >> 2, tig = lane & 3;
    float acc[2][8][4] = {};

    const unsigned asBase = (unsigned)__cvta_generic_to_shared(Asm);
    const unsigned bsBase = (unsigned)__cvta_generic_to_shared(Bsm);
    const unsigned aoffL = (unsigned)((wm + (lane & 15)) * 48 + (lane >> 4) * 16);
    const unsigned boffL = (unsigned)((wn + ((lane >> 4) << 3) + (lane & 7)) * 48
                                      + ((lane >> 3) & 1) * 16);
    const int srow = tid >> 1, sch = tid & 1;
    const bool aval = (bm + srow) < ga.M;
    const __nv_bfloat16* Agp = ga.A + (size_t)(bm + srow) * K + sch * 8;
    const __nv_bfloat16* Bgp = ga.Bt + (size_t)(bn + srow) * K + sch * 8;
    const unsigned daBase = asBase + (unsigned)(srow * 48 + sch * 16);
    const unsigned dbBase = bsBase + (unsigned)(srow * 48 + sch * 16);
    const int aSz = aval ? 16 : 0;

    auto issuePair = [&](int p) {
        int s0 = (2 * p) % 6;
        int k0 = p * 32;
        asm volatile("cp.async.ca.shared.global [%0], [%1], 16, %2;"
                     :: "r"(daBase + s0 * 6144), "l"(Agp + k0), "r"(aSz));
        asm volatile("cp.async.ca.shared.global [%0], [%1], 16, %2;"
                     :: "r"(daBase + (s0 + 1) * 6144), "l"(Agp + k0 + 16), "r"(aSz));
        asm volatile("cp.async.ca.shared.global [%0], [%1], 16;"
                     :: "r"(dbBase + s0 * 6144), "l"(Bgp + k0));
        asm volatile("cp.async.ca.shared.global [%0], [%1], 16;"
                     :: "r"(dbBase + (s0 + 1) * 6144), "l"(Bgp + k0 + 16));
        asm volatile("cp.async.commit_group;" ::: "memory");
    };

    const int TP = K >> 5;
    issuePair(0);
    issuePair(1);

    for (int p = 0; p < TP; p++) {
        asm volatile("cp.async.wait_group 1;" ::: "memory");
        __syncthreads();
#pragma unroll
        for (int sub = 0; sub < 2; sub++) {
            const int buf = (2 * p + sub) % 6;
            unsigned af[2][4], bfr[4][4];
            unsigned ab = asBase + (unsigned)(buf * 6144) + aoffL;
            ldsm4(af[0], ab);
            ldsm4(af[1], ab + 16 * 48);
            unsigned bb = bsBase + (unsigned)(buf * 6144) + boffL;
#pragma unroll
            for (int bt = 0; bt < 4; bt++) ldsm4(bfr[bt], bb + bt * 16 * 48);
#pragma unroll
            for (int mt = 0; mt < 2; mt++)
#pragma unroll
                for (int nt = 0; nt < 8; nt++)
                    mma16(acc[mt][nt], af[mt],
                          bfr[nt >> 1][(nt & 1) * 2], bfr[nt >> 1][(nt & 1) * 2 + 1]);
        }
        if (p + 2 < TP) issuePair(p + 2);
        else asm volatile("cp.async.commit_group;" ::: "memory");
    }

    // C write (bf16)
#pragma unroll
    for (int mt = 0; mt < 2; mt++) {
#pragma unroll
        for (int nt = 0; nt < 8; nt++) {
            int r0 = bm + wm + mt * 16 + gid;
            int c = bn + wn + nt * 8 + tig * 2;
            if (r0 < ga.M)
                *reinterpret_cast<unsigned*>(ga.C + (size_t)r0 * N + c) =
                    packbf(acc[mt][nt][0], acc[mt][nt][1]);
            if (r0 + 8 < ga.M)
                *reinterpret_cast<unsigned*>(ga.C + (size_t)(r0 + 8) * N + c) =
                    packbf(acc[mt][nt][2], acc[mt][nt][3]);
        }
    }

    // fused score epilogue (two scores; unique-writer stores)
    {
        const int pidx = (PS == 4) ? ((bn + wn) >> 6) : 0;
        float wpv[8][2], wqv[8][2];
#pragma unroll
        for (int nt = 0; nt < 8; nt++) {
            int c = bn + wn + nt * 8 + tig * 2;
            wpv[nt][0] = ga.wp[c]; wpv[nt][1] = ga.wp[c + 1];
            wqv[nt][0] = ga.wq[c]; wqv[nt][1] = ga.wq[c + 1];
        }
#pragma unroll
        for (int mt = 0; mt < 2; mt++) {
#pragma unroll
            for (int half = 0; half < 2; half++) {
                float p = 0.f, q = 0.f;
#pragma unroll
                for (int nt = 0; nt < 8; nt++) {
                    p += acc[mt][nt][half * 2 + 0] * wpv[nt][0]
                       + acc[mt][nt][half * 2 + 1] * wpv[nt][1];
                    q += acc[mt][nt][half * 2 + 0] * wqv[nt][0]
                       + acc[mt][nt][half * 2 + 1] * wqv[nt][1];
                }
                p += __shfl_xor_sync(0xffffffffu, p, 1);
                p += __shfl_xor_sync(0xffffffffu, p, 2);
                q += __shfl_xor_sync(0xffffffffu, q, 1);
                q += __shfl_xor_sync(0xffffffffu, q, 2);
                int r = bm + wm + mt * 16 + gid + half * 8;
                if (tig == 0 && r < ga.M) {
                    ga.P[(size_t)r * PS + pidx] = p;
                    ga.Q[(size_t)r * PS + pidx] = q;
                }
            }
        }
    }
}

// ------- layer1 edge attention: warp per edge; fused pe1 AND se2 epilogues -------
__global__ __launch_bounds__(256)
void edge_attn1(const int* __restrict__ el, const float* __restrict__ a2) {
    int e = blockIdx.x * 8 + (threadIdx.x >> 5);
    if (e >= N_EDGES_C) return;
    int lane = threadIdx.x & 31;
    int h = lane >> 3, jl = lane & 7;
    float se = g_se1[e * 4 + h];
    int ids[MAX_ARITY];
    float s[MAX_ARITY];
#pragma unroll
    for (int ai = 0; ai < MAX_ARITY; ai++) ids[ai] = el[e * MAX_ARITY + ai];
#pragma unroll
    for (int ai = 0; ai < MAX_ARITY; ai++)
        s[ai] = (ids[ai] > 0) ? lreluf(se + g_pn1[(ids[ai] - 1) * 4 + h]) : -1e9f;
    float m = s[0];
#pragma unroll
    for (int ai = 1; ai < MAX_ARITY; ai++) m = fmaxf(m, s[ai]);
    float wv[MAX_ARITY], den = 0.f;
#pragma unroll
    for (int ai = 0; ai < MAX_ARITY; ai++) { wv[ai] = expf(s[ai] - m); den += wv[ai]; }
    float inv = 1.f / den;
    float o[8] = {};
#pragma unroll
    for (int ai = 0; ai < MAX_ARITY; ai++) {
        if (ids[ai] > 0) {
            uint4 u = *reinterpret_cast<const uint4*>(
                g_hn1 + (size_t)(ids[ai] - 1) * 256 + lane * 8);
            float f[8]; unpack8(u, f);
            float wg = wv[ai] * inv;
#pragma unroll
            for (int i = 0; i < 8; i++) o[i] += wg * f[i];
        }
    }
    *reinterpret_cast<uint4*>(g_eo1 + (size_t)e * 256 + lane * 8) = pack8(o);
    // pe1[e,h] = eo1_row(head h part) . a2[h,64:128]
    float pe = 0.f;
#pragma unroll
    for (int i = 0; i < 8; i++) pe += o[i] * a2[h * 128 + 64 + jl * 8 + i];
    pe = seg8_sum(pe);
    if (jl == 0) g_pe1[e * 4 + h] = pe;
    // se2[e] = ELU(eo1_row) . vpe2  (full 256-wide dot, fp32, from registers)
    float s2 = 0.f;
#pragma unroll
    for (int i = 0; i < 8; i++) s2 += eluf(o[i]) * g_vpe2[lane * 8 + i];
    s2 = warp_sum(s2);
    if (lane == 0) g_se2[e] = s2;
}

// ------- layer1 node attention: warp per node, +ELU ------------------------------
__global__ __launch_bounds__(256)
void node_attn1(const int* __restrict__ nl) {
    int n = blockIdx.x * 8 + (threadIdx.x >> 5);
    if (n >= N_NODES_C) return;
    int lane = threadIdx.x & 31;
    int h = lane >> 3;
    float sn = g_sn1[n * 4 + h];
    int ids[MAX_DEG];
    float s[MAX_DEG];
#pragma unroll
    for (int di = 0; di < MAX_DEG; di++) ids[di] = nl[n * MAX_DEG + di];
#pragma unroll
    for (int di = 0; di < MAX_DEG; di++)
        s[di] = (ids[di] > 0) ? lreluf(sn + g_pe1[(ids[di] - 1) * 4 + h]) : -1e9f;
    float m = s[0];
#pragma unroll
    for (int di = 1; di < MAX_DEG; di++) m = fmaxf(m, s[di]);
    float wv[MAX_DEG], den = 0.f;
#pragma unroll
    for (int di = 0; di < MAX_DEG; di++) { wv[di] = expf(s[di] - m); den += wv[di]; }
    float inv = 1.f / den;
    float o[8] = {};
#pragma unroll
    for (int di = 0; di < MAX_DEG; di++) {
        if (ids[di] > 0) {
            uint4 u = *reinterpret_cast<const uint4*>(
                g_eo1 + (size_t)(ids[di] - 1) * 256 + lane * 8);
            float f[8]; unpack8(u, f);
            float wg = wv[di] * inv;
#pragma unroll
            for (int i = 0; i < 8; i++) o[i] += wg * f[i];
        }
    }
#pragma unroll
    for (int i = 0; i < 8; i++) o[i] = eluf(o[i]);
    *reinterpret_cast<uint4*>(g_no1 + (size_t)n * 256 + lane * 8) = pack8(o);
}

// ------- layer2 edge attention ----------------------------------------------------
__global__ __launch_bounds__(256)
void edge_attn2(const int* __restrict__ el, const float* __restrict__ a2o) {
    int e = blockIdx.x * 8 + (threadIdx.x >> 5);
    if (e >= N_EDGES_C) return;
    int lane = threadIdx.x & 31;
    float se = g_se2[e];
    int ids[MAX_ARITY];
    float s[MAX_ARITY];
#pragma unroll
    for (int ai = 0; ai < MAX_ARITY; ai++) ids[ai] = el[e * MAX_ARITY + ai];
#pragma unroll
    for (int ai = 0; ai < MAX_ARITY; ai++)
        s[ai] = (ids[ai] > 0) ? lreluf(se + g_pn2[ids[ai] - 1]) : -1e9f;
    float m = s[0];
#pragma unroll
    for (int ai = 1; ai < MAX_ARITY; ai++) m = fmaxf(m, s[ai]);
    float wv[MAX_ARITY], den = 0.f;
#pragma unroll
    for (int ai = 0; ai < MAX_ARITY; ai++) { wv[ai] = expf(s[ai] - m); den += wv[ai]; }
    float inv = 1.f / den;
    float o[4] = {};
#pragma unroll
    for (int ai = 0; ai < MAX_ARITY; ai++) {
        if (ids[ai] > 0) {
            uint2 u = *reinterpret_cast<const uint2*>(
                g_hn2 + (size_t)(ids[ai] - 1) * 128 + lane * 4);
            float2 x = unpackbf(u.x), y = unpackbf(u.y);
            float wg = wv[ai] * inv;
            o[0] += wg * x.x; o[1] += wg * x.y; o[2] += wg * y.x; o[3] += wg * y.y;
        }
    }
    *reinterpret_cast<float4*>(g_eo2 + (size_t)e * 128 + lane * 4) =
        make_float4(o[0], o[1], o[2], o[3]);
    float pe = 0.f;
#pragma unroll
    for (int i = 0; i < 4; i++) pe += o[i] * a2o[128 + lane * 4 + i];
    pe = warp_sum(pe);
    if (lane == 0) g_pe2[e] = pe;
}

// ------- layer2 node attention: pruned to batch-referenced -----------------------
__global__ __launch_bounds__(256)
void node_attn2(const int* __restrict__ nl) {
    int n = blockIdx.x * 8 + (threadIdx.x >> 5);
    if (n >= N_NODES_C) return;
    if (!g_mask[n]) return;
    int lane = threadIdx.x & 31;
    float sn = g_sn2[n];
    int ids[MAX_DEG];
    float s[MAX_DEG];
#pragma unroll
    for (int di = 0; di < MAX_DEG; di++) ids[di] = nl[n * MAX_DEG + di];
#pragma unroll
    for (int di = 0; di < MAX_DEG; di++)
        s[di] = (ids[di] > 0) ? lreluf(sn + g_pe2[ids[di] - 1]) : -1e9f;
    float m = s[0];
#pragma unroll
    for (int di = 1; di < MAX_DEG; di++) m = fmaxf(m, s[di]);
    float wv[MAX_DEG], den = 0.f;
#pragma unroll
    for (int di = 0; di < MAX_DEG; di++) { wv[di] = expf(s[di] - m); den += wv[di]; }
    float inv = 1.f / den;
    float o[4] = {};
#pragma unroll
    for (int di = 0; di < MAX_DEG; di++) {
        if (ids[di] > 0) {
            float4 x = *reinterpret_cast<const float4*>(
                g_eo2 + (size_t)(ids[di] - 1) * 128 + lane * 4);
            float wg = wv[di] * inv;
            o[0] += wg * x.x; o[1] += wg * x.y; o[2] += wg * x.z; o[3] += wg * x.w;
        }
    }
    *reinterpret_cast<float4*>(g_no2 + (size_t)n * 128 + lane * 4) =
        make_float4(o[0], o[1], o[2], o[3]);
}

// ---------------- final batch gather ----------------
__global__ __launch_bounds__(128)
void gather_out(const int* __restrict__ bi, float* __restrict__ out) {
    int b = blockIdx.x;
    int t = threadIdx.x;
    __shared__ int ids[7];
    __shared__ int lastnz;
    if (t < 7) ids[t] = bi[b * 7 + t];
    __syncthreads();
    if (t == 0) {
        int ln = 0;
#pragma unroll
        for (int j = 1; j < 7; j++) if (ids[j] != 0) ln = j;
        lastnz = ln;
    }
    __syncthreads();
    int ln = lastnz;
    out[(size_t)b * 896 + t] = eluf(g_eo2[(size_t)(ids[0] - 1) * 128 + t]);
#pragma unroll
    for (int a = 1; a < 7; a++) {
        int nid = ids[a] - 1;
        if (nid < 0) nid += N_NODES_C;
        float g = (a <= ln) ? eluf(g_no2[(size_t)nid * 128 + t]) : 1.0f;
        out[(size_t)b * 896 + a * 128 + t] = g;
    }
}

// ---------------- launch ----------------
extern "C" void kernel_launch(void* const* d_in, const int* in_sizes, int n_in,
                              void* d_out, int out_size) {
    (void)in_sizes; (void)n_in; (void)out_size;
    const int*   bi    = (const int*)d_in[0];
    const int*   el    = (const int*)d_in[1];
    const int*   nl    = (const int*)d_in[2];
    const float* nemb  = (const float*)d_in[3];
    const float* eemb  = (const float*)d_in[4];
    const float* Wn    = (const float*)d_in[5];
    const float* We    = (const float*)d_in[6];
    const float* a1    = (const float*)d_in[7];
    const float* a2    = (const float*)d_in[8];
    const float* Wn_o  = (const float*)d_in[9];
    const float* We_o  = (const float*)d_in[10];
    const float* a1_o  = (const float*)d_in[11];
    const float* a2_o  = (const float*)d_in[12];
    float* out = (float*)d_out;

    __nv_bfloat16 *embn, *embe, *hn1, *no1, *hn2, *bt1n, *bt2n;
    float *pn1, *sn1, *se1, *pn2, *sn2;
    float *wpn1, *wqn1, *wpn2, *wqn2, *vpe1;
    cudaGetSymbolAddress((void**)&embn, g_embn);
    cudaGetSymbolAddress((void**)&embe, g_embe);
    cudaGetSymbolAddress((void**)&hn1, g_hn1);
    cudaGetSymbolAddress((void**)&no1, g_no1);
    cudaGetSymbolAddress((void**)&hn2, g_hn2);
    cudaGetSymbolAddress((void**)&pn1, g_pn1);
    cudaGetSymbolAddress((void**)&sn1, g_sn1);
    cudaGetSymbolAddress((void**)&se1, g_se1);
    cudaGetSymbolAddress((void**)&pn2, g_pn2);
    cudaGetSymbolAddress((void**)&sn2, g_sn2);
    cudaGetSymbolAddress((void**)&wpn1, g_wpn1);
    cudaGetSymbolAddress((void**)&wqn1, g_wqn1);
    cudaGetSymbolAddress((void**)&wpn2, g_wpn2);
    cudaGetSymbolAddress((void**)&wqn2, g_wqn2);
    cudaGetSymbolAddress((void**)&vpe1, g_vpe1);
    cudaGetSymbolAddress((void**)&bt1n, g_Bt1n);
    cudaGetSymbolAddress((void**)&bt2n, g_Bt2n);

    static bool attr_set = false;
    if (!attr_set) {
        cudaFuncSetAttribute(gemm_gv, cudaFuncAttributeMaxDynamicSharedMemorySize,
                             73728);
        attr_set = true;
    }

    prep<<<3125, 256>>>(Wn, We, Wn_o, We_o, a1, a2, a1_o, a2_o, nemb, eemb);
    mark_nodes<<<96, 256>>>(bi);

    // ---- layer1: node GEMM (782 blocks) + se1 GEMV (391 blocks), one launch ----
    GArgs n1{embn, bt1n, hn1, N_NODES_C, wpn1, wqn1, pn1, sn1, 391};
    GvArgs v1{embe, N_EDGES_C, vpe1, se1};
    gemm_gv<<<782 + 391, 256, 73728>>>(n1, v1, 782, 256, 128, 4);

    edge_attn1<<<3125, 256>>>(el, a2);     // writes eo1, pe1, AND se2
    node_attn1<<<6250, 256>>>(nl);

    // ---- layer2: node GEMM only (edge scores already done in edge_attn1) ----
    GArgs n2{no1, bt2n, hn2, N_NODES_C, wpn2, wqn2, pn2, sn2, 391};
    GvArgs v2{nullptr, 0, nullptr, nullptr};
    gemm_gv<<<391, 256, 73728>>>(n2, v2, 391, 128, 256, 1);

    edge_attn2<<<3125, 256>>>(el, a1_o);
    node_attn2<<<6250, 256>>>(nl);

    gather_out<<<BATCH_C, 128>>>(bi, out);
}

// round 15
// speedup vs baseline: 1.1874x; 1.0911x over previous
#include <cuda_runtime.h>
#include <cuda_bf16.h>
#include <cstdint>

#define N_NODES_C 50000
#define N_EDGES_C 25000
#define MAX_ARITY 6
#define MAX_DEG 8
#define BATCH_C 4096

// ---------------- scratch (device globals; no allocations allowed) ----------------
__device__ __align__(256) __nv_bfloat16 g_embn[N_NODES_C * 128];
__device__ __align__(256) __nv_bfloat16 g_embe[N_EDGES_C * 128];
__device__ __align__(256) __nv_bfloat16 g_hn1[N_NODES_C * 256];
__device__ __align__(256) __nv_bfloat16 g_eo1[N_EDGES_C * 256];
__device__ __align__(256) __nv_bfloat16 g_eo1e[N_EDGES_C * 256];
__device__ __align__(256) __nv_bfloat16 g_no1[N_NODES_C * 256];
__device__ __align__(256) __nv_bfloat16 g_hn2[N_NODES_C * 128];
__device__ __align__(256) float g_eo2[N_EDGES_C * 128];
__device__ __align__(256) float g_no2[N_NODES_C * 128];
// pre-transposed bf16 weights, [n][k]
__device__ __align__(256) __nv_bfloat16 g_Bt1n[256 * 128];
__device__ __align__(256) __nv_bfloat16 g_Bt1e[256 * 128];
__device__ __align__(256) __nv_bfloat16 g_Bt2n[128 * 256];
__device__ __align__(256) __nv_bfloat16 g_Bt2e[128 * 256];
// score-weight vectors
__device__ float g_wpn1[256];
__device__ float g_wqn1[256];
__device__ float g_wpe1[256];
__device__ float g_wpn2[128];
__device__ float g_wqn2[128];
__device__ float g_wpe2[128];
// scalar score caches (unique-writer)
__device__ float g_pn1[N_NODES_C * 4];
__device__ float g_sn1[N_NODES_C * 4];
__device__ float g_se1[N_EDGES_C * 4];
__device__ float g_pe1[N_EDGES_C * 4];
__device__ float g_pn2[N_NODES_C];
__device__ float g_sn2[N_NODES_C];
__device__ float g_se2[N_EDGES_C];
__device__ float g_pe2[N_EDGES_C];
__device__ unsigned char g_mask[N_NODES_C];

// ---------------- helpers ----------------
__device__ __forceinline__ float warp_sum(float v) {
#pragma unroll
    for (int o = 16; o > 0; o >>= 1) v += __shfl_xor_sync(0xffffffffu, v, o);
    return v;
}
__device__ __forceinline__ float seg8_sum(float v) {
#pragma unroll
    for (int o = 4; o > 0; o >>= 1) v += __shfl_xor_sync(0xffffffffu, v, o);
    return v;
}
__device__ __forceinline__ float eluf(float x)  { return x > 0.f ? x : expm1f(x); }
__device__ __forceinline__ float lreluf(float x){ return x > 0.f ? x : 0.2f * x; }

__device__ __forceinline__ void ldsm4(unsigned r[4], unsigned addr) {
    asm volatile("ldmatrix.sync.aligned.m8n8.x4.shared.b16 {%0,%1,%2,%3},[%4];"
                 : "=r"(r[0]), "=r"(r[1]), "=r"(r[2]), "=r"(r[3]) : "r"(addr));
}
__device__ __forceinline__ void mma16(float c[4], const unsigned a[4],
                                      unsigned b0, unsigned b1) {
    asm volatile(
        "mma.sync.aligned.m16n8k16.row.col.f32.bf16.bf16.f32 "
        "{%0,%1,%2,%3},{%4,%5,%6,%7},{%8,%9},{%0,%1,%2,%3};"
        : "+f"(c[0]), "+f"(c[1]), "+f"(c[2]), "+f"(c[3])
        : "r"(a[0]), "r"(a[1]), "r"(a[2]), "r"(a[3]), "r"(b0), "r"(b1));
}

__device__ __forceinline__ unsigned packbf(float a, float b) {
    __nv_bfloat162 h = __floats2bfloat162_rn(a, b);
    return *reinterpret_cast<unsigned*>(&h);
}
__device__ __forceinline__ float2 unpackbf(unsigned u) {
    return __bfloat1622float2(*reinterpret_cast<__nv_bfloat162*>(&u));
}
__device__ __forceinline__ void unpack8(uint4 u, float f[8]) {
    float2 a = unpackbf(u.x), b = unpackbf(u.y), c = unpackbf(u.z), d = unpackbf(u.w);
    f[0] = a.x; f[1] = a.y; f[2] = b.x; f[3] = b.y;
    f[4] = c.x; f[5] = c.y; f[6] = d.x; f[7] = d.y;
}
__device__ __forceinline__ uint4 pack8(const float f[8]) {
    uint4 u;
    u.x = packbf(f[0], f[1]); u.y = packbf(f[2], f[3]);
    u.z = packbf(f[4], f[5]); u.w = packbf(f[6], f[7]);
    return u;
}

// ---------------- prep ----------------
__global__ void prep(const float* __restrict__ Wn, const float* __restrict__ We,
                     const float* __restrict__ Wn_o, const float* __restrict__ We_o,
                     const float* __restrict__ a1, const float* __restrict__ a2,
                     const float* __restrict__ a1o, const float* __restrict__ a2o) {
    int i = blockIdx.x * 256 + threadIdx.x;
    if (i < 32768) {
        int c = i >> 7, k = i & 127;
        int h = c >> 6, j = c & 63;
        g_Bt1n[i] = __float2bfloat16_rn(Wn[h * 8192 + k * 64 + j]);
        g_Bt1e[i] = __float2bfloat16_rn(We[h * 8192 + k * 64 + j]);
        int n2 = i >> 8, k2 = i & 255;
        g_Bt2n[i] = __float2bfloat16_rn(Wn_o[k2 * 128 + n2]);
        g_Bt2e[i] = __float2bfloat16_rn(We_o[k2 * 128 + n2]);
    }
    if (i < 256) {
        int h = i >> 6, j = i & 63;
        g_wpn1[i] = a1[h * 128 + 64 + j];
        g_wqn1[i] = a2[h * 128 + j];
        g_wpe1[i] = a1[h * 128 + j];
    }
    if (i < 128) {
        g_wpn2[i] = a1o[128 + i];
        g_wqn2[i] = a2o[i];
        g_wpe2[i] = a1o[i];
    }
    if (i < N_NODES_C) g_mask[i] = 0;
}

// ---------------- convert embeddings fp32 -> bf16, and mark batch nodes ----------
__global__ void conv_emb(const float* __restrict__ nemb, const float* __restrict__ eemb,
                         const int* __restrict__ bi) {
    int i = blockIdx.x * 256 + threadIdx.x;
    if (i < (N_NODES_C * 128) / 8) {
        float4 v0 = *reinterpret_cast<const float4*>(nemb + i * 8);
        float4 v1 = *reinterpret_cast<const float4*>(nemb + i * 8 + 4);
        uint4 u;
        u.x = packbf(v0.x, v0.y); u.y = packbf(v0.z, v0.w);
        u.z = packbf(v1.x, v1.y); u.w = packbf(v1.z, v1.w);
        *reinterpret_cast<uint4*>(g_embn + i * 8) = u;
    }
    if (i < (N_EDGES_C * 128) / 8) {
        float4 v0 = *reinterpret_cast<const float4*>(eemb + i * 8);
        float4 v1 = *reinterpret_cast<const float4*>(eemb + i * 8 + 4);
        uint4 u;
        u.x = packbf(v0.x, v0.y); u.y = packbf(v0.z, v0.w);
        u.z = packbf(v1.x, v1.y); u.w = packbf(v1.z, v1.w);
        *reinterpret_cast<uint4*>(g_embe + i * 8) = u;
    }
    if (i < BATCH_C * 6) {
        int b = i / 6, a = i % 6 + 1;
        int nid = bi[b * 7 + a] - 1;
        if (nid < 0) nid += N_NODES_C;
        g_mask[nid] = 1;
    }
}

// ---------------- fused dual-problem BF16 GEMM ------------------------------------
// BM=128, BN=128, warp tile 32x64, 6-stage cp.async (dynamic smem, 72KB),
// barrier every 2 K-iters. Two independent problems in one launch.
struct GArgs {
    const __nv_bfloat16* A;
    const __nv_bfloat16* Bt;
    __nv_bfloat16* C;
    int M;
    const float* wp;
    const float* wq;
    float* P;
    float* Q;
    int writeC;   // 0/1
    int scores;   // 1 or 2
    int gx;       // blocks in x for this problem
};

__global__ __launch_bounds__(256, 2)
void gemm_dual(GArgs ga1, GArgs ga2, int split, int N, int K, int PS) {
    extern __shared__ __align__(16) __nv_bfloat16 smem[];
    __nv_bfloat16* Asm = smem;                    // [6][128][24]
    __nv_bfloat16* Bsm = smem + 6 * 128 * 24;     // [6][128][24]

    const bool first = (int)blockIdx.x < split;
    const GArgs ga = first ? ga1 : ga2;
    const int bl = first ? blockIdx.x : blockIdx.x - split;
    const int bx = bl % ga.gx, by = bl / ga.gx;
    const int bm = bx * 128, bn = by * 128;

    const int tid = threadIdx.x;
    const int w = tid >> 5, lane = tid & 31;
    const int wm = (w >> 1) * 32, wn = (w & 1) * 64;
    const int gid = lane >> 2, tig = lane & 3;
    float acc[2][8][4] = {};

    const unsigned asBase = (unsigned)__cvta_generic_to_shared(Asm);
    const unsigned bsBase = (unsigned)__cvta_generic_to_shared(Bsm);
    const unsigned aoffL = (unsigned)((wm + (lane & 15)) * 48 + (lane >> 4) * 16);
    const unsigned boffL = (unsigned)((wn + ((lane >> 4) << 3) + (lane & 7)) * 48
                                      + ((lane >> 3) & 1) * 16);
    const int srow = tid >> 1, sch = tid & 1;
    const bool aval = (bm + srow) < ga.M;
    const __nv_bfloat16* Agp = ga.A + (size_t)(bm + srow) * K + sch * 8;
    const __nv_bfloat16* Bgp = ga.Bt + (size_t)(bn + srow) * K + sch * 8;
    const unsigned daBase = asBase + (unsigned)(srow * 48 + sch * 16);
    const unsigned dbBase = bsBase + (unsigned)(srow * 48 + sch * 16);
    const int aSz = aval ? 16 : 0;

    auto issuePair = [&](int p) {
        int s0 = (2 * p) % 6;
        int k0 = p * 32;
        asm volatile("cp.async.ca.shared.global [%0], [%1], 16, %2;"
                     :: "r"(daBase + s0 * 6144), "l"(Agp + k0), "r"(aSz));
        asm volatile("cp.async.ca.shared.global [%0], [%1], 16, %2;"
                     :: "r"(daBase + (s0 + 1) * 6144), "l"(Agp + k0 + 16), "r"(aSz));
        asm volatile("cp.async.ca.shared.global [%0], [%1], 16;"
                     :: "r"(dbBase + s0 * 6144), "l"(Bgp + k0));
        asm volatile("cp.async.ca.shared.global [%0], [%1], 16;"
                     :: "r"(dbBase + (s0 + 1) * 6144), "l"(Bgp + k0 + 16));
        asm volatile("cp.async.commit_group;" ::: "memory");
    };

    const int TP = K >> 5;
    issuePair(0);
    issuePair(1);

    for (int p = 0; p < TP; p++) {
        asm volatile("cp.async.wait_group 1;" ::: "memory");
        __syncthreads();
#pragma unroll
        for (int sub = 0; sub < 2; sub++) {
            const int buf = (2 * p + sub) % 6;
            unsigned af[2][4], bfr[4][4];
            unsigned ab = asBase + (unsigned)(buf * 6144) + aoffL;
            ldsm4(af[0], ab);
            ldsm4(af[1], ab + 16 * 48);
            unsigned bb = bsBase + (unsigned)(buf * 6144) + boffL;
#pragma unroll
            for (int bt = 0; bt < 4; bt++) ldsm4(bfr[bt], bb + bt * 16 * 48);
#pragma unroll
            for (int mt = 0; mt < 2; mt++)
#pragma unroll
                for (int nt = 0; nt < 8; nt++)
                    mma16(acc[mt][nt], af[mt],
                          bfr[nt >> 1][(nt & 1) * 2], bfr[nt >> 1][(nt & 1) * 2 + 1]);
        }
        if (p + 2 < TP) issuePair(p + 2);
        else asm volatile("cp.async.commit_group;" ::: "memory");
    }

    if (ga.writeC) {
        __nv_bfloat16* Cb = ga.C;
#pragma unroll
        for (int mt = 0; mt < 2; mt++) {
#pragma unroll
            for (int nt = 0; nt < 8; nt++) {
                int r0 = bm + wm + mt * 16 + gid;
                int c = bn + wn + nt * 8 + tig * 2;
                if (r0 < ga.M)
                    *reinterpret_cast<unsigned*>(Cb + (size_t)r0 * N + c) =
                        packbf(acc[mt][nt][0], acc[mt][nt][1]);
                if (r0 + 8 < ga.M)
                    *reinterpret_cast<unsigned*>(Cb + (size_t)(r0 + 8) * N + c) =
                        packbf(acc[mt][nt][2], acc[mt][nt][3]);
            }
        }
    }

    {   // fused score epilogue
        const int pidx = (PS == 4) ? ((bn + wn) >> 6) : 0;
        const bool two = (ga.scores == 2);
        float wpv[8][2], wqv[8][2];
#pragma unroll
        for (int nt = 0; nt < 8; nt++) {
            int c = bn + wn + nt * 8 + tig * 2;
            wpv[nt][0] = ga.wp[c]; wpv[nt][1] = ga.wp[c + 1];
            if (two) { wqv[nt][0] = ga.wq[c]; wqv[nt][1] = ga.wq[c + 1]; }
        }
#pragma unroll
        for (int mt = 0; mt < 2; mt++) {
#pragma unroll
            for (int half = 0; half < 2; half++) {
                float p = 0.f, q = 0.f;
#pragma unroll
                for (int nt = 0; nt < 8; nt++) {
                    p += acc[mt][nt][half * 2 + 0] * wpv[nt][0]
                       + acc[mt][nt][half * 2 + 1] * wpv[nt][1];
                    if (two)
                        q += acc[mt][nt][half * 2 + 0] * wqv[nt][0]
                           + acc[mt][nt][half * 2 + 1] * wqv[nt][1];
                }
                p += __shfl_xor_sync(0xffffffffu, p, 1);
                p += __shfl_xor_sync(0xffffffffu, p, 2);
                if (two) {
                    q += __shfl_xor_sync(0xffffffffu, q, 1);
                    q += __shfl_xor_sync(0xffffffffu, q, 2);
                }
                int r = bm + wm + mt * 16 + gid + half * 8;
                if (tig == 0 && r < ga.M) {
                    ga.P[(size_t)r * PS + pidx] = p;    // unique writer
                    if (two) ga.Q[(size_t)r * PS + pidx] = q;
                }
            }
        }
    }
}

// ------- layer1 edge attention: warp per edge; writes raw + ELU copies -----------
__global__ __launch_bounds__(256)
void edge_attn1(const int* __restrict__ el, const float* __restrict__ a2) {
    int e = blockIdx.x * 8 + (threadIdx.x >> 5);
    if (e >= N_EDGES_C) return;
    int lane = threadIdx.x & 31;
    int h = lane >> 3, jl = lane & 7;
    float se = g_se1[e * 4 + h];
    int ids[MAX_ARITY];
    float s[MAX_ARITY];
#pragma unroll
    for (int ai = 0; ai < MAX_ARITY; ai++) ids[ai] = el[e * MAX_ARITY + ai];
#pragma unroll
    for (int ai = 0; ai < MAX_ARITY; ai++)
        s[ai] = (ids[ai] > 0) ? lreluf(se + g_pn1[(ids[ai] - 1) * 4 + h]) : -1e9f;
    float m = s[0];
#pragma unroll
    for (int ai = 1; ai < MAX_ARITY; ai++) m = fmaxf(m, s[ai]);
    float wv[MAX_ARITY], den = 0.f;
#pragma unroll
    for (int ai = 0; ai < MAX_ARITY; ai++) { wv[ai] = expf(s[ai] - m); den += wv[ai]; }
    float inv = 1.f / den;
    float o[8] = {};
#pragma unroll
    for (int ai = 0; ai < MAX_ARITY; ai++) {
        if (ids[ai] > 0) {
            uint4 u = *reinterpret_cast<const uint4*>(
                g_hn1 + (size_t)(ids[ai] - 1) * 256 + lane * 8);
            float f[8]; unpack8(u, f);
            float wg = wv[ai] * inv;
#pragma unroll
            for (int i = 0; i < 8; i++) o[i] += wg * f[i];
        }
    }
    *reinterpret_cast<uint4*>(g_eo1 + (size_t)e * 256 + lane * 8) = pack8(o);
    float oe[8];
#pragma unroll
    for (int i = 0; i < 8; i++) oe[i] = eluf(o[i]);
    *reinterpret_cast<uint4*>(g_eo1e + (size_t)e * 256 + lane * 8) = pack8(oe);
    float pe = 0.f;
#pragma unroll
    for (int i = 0; i < 8; i++) pe += o[i] * a2[h * 128 + 64 + jl * 8 + i];
    pe = seg8_sum(pe);
    if (jl == 0) g_pe1[e * 4 + h] = pe;
}

// ------- layer1 node attention: warp per node, +ELU ------------------------------
__global__ __launch_bounds__(256)
void node_attn1(const int* __restrict__ nl) {
    int n = blockIdx.x * 8 + (threadIdx.x >> 5);
    if (n >= N_NODES_C) return;
    int lane = threadIdx.x & 31;
    int h = lane >> 3;
    float sn = g_sn1[n * 4 + h];
    int ids[MAX_DEG];
    float s[MAX_DEG];
#pragma unroll
    for (int di = 0; di < MAX_DEG; di++) ids[di] = nl[n * MAX_DEG + di];
#pragma unroll
    for (int di = 0; di < MAX_DEG; di++)
        s[di] = (ids[di] > 0) ? lreluf(sn + g_pe1[(ids[di] - 1) * 4 + h]) : -1e9f;
    float m = s[0];
#pragma unroll
    for (int di = 1; di < MAX_DEG; di++) m = fmaxf(m, s[di]);
    float wv[MAX_DEG], den = 0.f;
#pragma unroll
    for (int di = 0; di < MAX_DEG; di++) { wv[di] = expf(s[di] - m); den += wv[di]; }
    float inv = 1.f / den;
    float o[8] = {};
#pragma unroll
    for (int di = 0; di < MAX_DEG; di++) {
        if (ids[di] > 0) {
            uint4 u = *reinterpret_cast<const uint4*>(
                g_eo1 + (size_t)(ids[di] - 1) * 256 + lane * 8);
            float f[8]; unpack8(u, f);
            float wg = wv[di] * inv;
#pragma unroll
            for (int i = 0; i < 8; i++) o[i] += wg * f[i];
        }
    }
#pragma unroll
    for (int i = 0; i < 8; i++) o[i] = eluf(o[i]);
    *reinterpret_cast<uint4*>(g_no1 + (size_t)n * 256 + lane * 8) = pack8(o);
}

// ------- layer2 edge attention ----------------------------------------------------
__global__ __launch_bounds__(256)
void edge_attn2(const int* __restrict__ el, const float* __restrict__ a2o) {
    int e = blockIdx.x * 8 + (threadIdx.x >> 5);
    if (e >= N_EDGES_C) return;
    int lane = threadIdx.x & 31;
    float se = g_se2[e];
    int ids[MAX_ARITY];
    float s[MAX_ARITY];
#pragma unroll
    for (int ai = 0; ai < MAX_ARITY; ai++) ids[ai] = el[e * MAX_ARITY + ai];
#pragma unroll
    for (int ai = 0; ai < MAX_ARITY; ai++)
        s[ai] = (ids[ai] > 0) ? lreluf(se + g_pn2[ids[ai] - 1]) : -1e9f;
    float m = s[0];
#pragma unroll
    for (int ai = 1; ai < MAX_ARITY; ai++) m = fmaxf(m, s[ai]);
    float wv[MAX_ARITY], den = 0.f;
#pragma unroll
    for (int ai = 0; ai < MAX_ARITY; ai++) { wv[ai] = expf(s[ai] - m); den += wv[ai]; }
    float inv = 1.f / den;
    float o[4] = {};
#pragma unroll
    for (int ai = 0; ai < MAX_ARITY; ai++) {
        if (ids[ai] > 0) {
            uint2 u = *reinterpret_cast<const uint2*>(
                g_hn2 + (size_t)(ids[ai] - 1) * 128 + lane * 4);
            float2 x = unpackbf(u.x), y = unpackbf(u.y);
            float wg = wv[ai] * inv;
            o[0] += wg * x.x; o[1] += wg * x.y; o[2] += wg * y.x; o[3] += wg * y.y;
        }
    }
    *reinterpret_cast<float4*>(g_eo2 + (size_t)e * 128 + lane * 4) =
        make_float4(o[0], o[1], o[2], o[3]);
    float pe = 0.f;
#pragma unroll
    for (int i = 0; i < 4; i++) pe += o[i] * a2o[128 + lane * 4 + i];
    pe = warp_sum(pe);
    if (lane == 0) g_pe2[e] = pe;
}

// ------- layer2 node attention: pruned to batch-referenced -----------------------
__global__ __launch_bounds__(256)
void node_attn2(const int* __restrict__ nl) {
    int n = blockIdx.x * 8 + (threadIdx.x >> 5);
    if (n >= N_NODES_C) return;
    if (!g_mask[n]) return;
    int lane = threadIdx.x & 31;
    float sn = g_sn2[n];
    int ids[MAX_DEG];
    float s[MAX_DEG];
#pragma unroll
    for (int di = 0; di < MAX_DEG; di++) ids[di] = nl[n * MAX_DEG + di];
#pragma unroll
    for (int di = 0; di < MAX_DEG; di++)
        s[di] = (ids[di] > 0) ? lreluf(sn + g_pe2[ids[di] - 1]) : -1e9f;
    float m = s[0];
#pragma unroll
    for (int di = 1; di < MAX_DEG; di++) m = fmaxf(m, s[di]);
    float wv[MAX_DEG], den = 0.f;
#pragma unroll
    for (int di = 0; di < MAX_DEG; di++) { wv[di] = expf(s[di] - m); den += wv[di]; }
    float inv = 1.f / den;
    float o[4] = {};
#pragma unroll
    for (int di = 0; di < MAX_DEG; di++) {
        if (ids[di] > 0) {
            float4 x = *reinterpret_cast<const float4*>(
                g_eo2 + (size_t)(ids[di] - 1) * 128 + lane * 4);
            float wg = wv[di] * inv;
            o[0] += wg * x.x; o[1] += wg * x.y; o[2] += wg * x.z; o[3] += wg * x.w;
        }
    }
    *reinterpret_cast<float4*>(g_no2 + (size_t)n * 128 + lane * 4) =
        make_float4(o[0], o[1], o[2], o[3]);
}

// ---------------- final batch gather ----------------
__global__ __launch_bounds__(128)
void gather_out(const int* __restrict__ bi, float* __restrict__ out) {
    int b = blockIdx.x;
    int t = threadIdx.x;
    __shared__ int ids[7];
    __shared__ int lastnz;
    if (t < 7) ids[t] = bi[b * 7 + t];
    __syncthreads();
    if (t == 0) {
        int ln = 0;
#pragma unroll
        for (int j = 1; j < 7; j++) if (ids[j] != 0) ln = j;
        lastnz = ln;
    }
    __syncthreads();
    int ln = lastnz;
    out[(size_t)b * 896 + t] = eluf(g_eo2[(size_t)(ids[0] - 1) * 128 + t]);
#pragma unroll
    for (int a = 1; a < 7; a++) {
        int nid = ids[a] - 1;
        if (nid < 0) nid += N_NODES_C;
        float g = (a <= ln) ? eluf(g_no2[(size_t)nid * 128 + t]) : 1.0f;
        out[(size_t)b * 896 + a * 128 + t] = g;
    }
}

// ---------------- launch ----------------
extern "C" void kernel_launch(void* const* d_in, const int* in_sizes, int n_in,
                              void* d_out, int out_size) {
    (void)in_sizes; (void)n_in; (void)out_size;
    const int*   bi    = (const int*)d_in[0];
    const int*   el    = (const int*)d_in[1];
    const int*   nl    = (const int*)d_in[2];
    const float* nemb  = (const float*)d_in[3];
    const float* eemb  = (const float*)d_in[4];
    const float* Wn    = (const float*)d_in[5];
    const float* We    = (const float*)d_in[6];
    const float* a1    = (const float*)d_in[7];
    const float* a2    = (const float*)d_in[8];
    const float* Wn_o  = (const float*)d_in[9];
    const float* We_o  = (const float*)d_in[10];
    const float* a1_o  = (const float*)d_in[11];
    const float* a2_o  = (const float*)d_in[12];
    float* out = (float*)d_out;

    __nv_bfloat16 *embn, *embe, *hn1, *eo1e, *no1, *hn2;
    __nv_bfloat16 *bt1n, *bt1e, *bt2n, *bt2e;
    float *pn1, *sn1, *se1, *pn2, *sn2, *se2;
    float *wpn1, *wqn1, *wpe1, *wpn2, *wqn2, *wpe2;
    cudaGetSymbolAddress((void**)&embn, g_embn);
    cudaGetSymbolAddress((void**)&embe, g_embe);
    cudaGetSymbolAddress((void**)&hn1, g_hn1);
    cudaGetSymbolAddress((void**)&eo1e, g_eo1e);
    cudaGetSymbolAddress((void**)&no1, g_no1);
    cudaGetSymbolAddress((void**)&hn2, g_hn2);
    cudaGetSymbolAddress((void**)&pn1, g_pn1);
    cudaGetSymbolAddress((void**)&sn1, g_sn1);
    cudaGetSymbolAddress((void**)&se1, g_se1);
    cudaGetSymbolAddress((void**)&pn2, g_pn2);
    cudaGetSymbolAddress((void**)&sn2, g_sn2);
    cudaGetSymbolAddress((void**)&se2, g_se2);
    cudaGetSymbolAddress((void**)&wpn1, g_wpn1);
    cudaGetSymbolAddress((void**)&wqn1, g_wqn1);
    cudaGetSymbolAddress((void**)&wpe1, g_wpe1);
    cudaGetSymbolAddress((void**)&wpn2, g_wpn2);
    cudaGetSymbolAddress((void**)&wqn2, g_wqn2);
    cudaGetSymbolAddress((void**)&wpe2, g_wpe2);
    cudaGetSymbolAddress((void**)&bt1n, g_Bt1n);
    cudaGetSymbolAddress((void**)&bt1e, g_Bt1e);
    cudaGetSymbolAddress((void**)&bt2n, g_Bt2n);
    cudaGetSymbolAddress((void**)&bt2e, g_Bt2e);

    static bool attr_set = false;
    if (!attr_set) {
        cudaFuncSetAttribute(gemm_dual, cudaFuncAttributeMaxDynamicSharedMemorySize,
                             73728);
        attr_set = true;
    }

    prep<<<782, 256>>>(Wn, We, Wn_o, We_o, a1, a2, a1_o, a2_o);
    conv_emb<<<3125, 256>>>(nemb, eemb, bi);

    // ---- layer1: fused node+edge projection GEMMs ----
    GArgs n1{embn, bt1n, hn1, N_NODES_C, wpn1, wqn1, pn1, sn1, 1, 2, 391};
    GArgs e1{embe, bt1e, nullptr, N_EDGES_C, wpe1, nullptr, se1, nullptr, 0, 1, 196};
    gemm_dual<<<782 + 392, 256, 73728>>>(n1, e1, 782, 256, 128, 4);

    edge_attn1<<<3125, 256>>>(el, a2);
    node_attn1<<<6250, 256>>>(nl);

    // ---- layer2: fused node+edge projection GEMMs ----
    GArgs n2{no1, bt2n, hn2, N_NODES_C, wpn2, wqn2, pn2, sn2, 1, 2, 391};
    GArgs e2{eo1e, bt2e, nullptr, N_EDGES_C, wpe2, nullptr, se2, nullptr, 0, 1, 196};
    gemm_dual<<<391 + 196, 256, 73728>>>(n2, e2, 391, 128, 256, 1);

    edge_attn2<<<3125, 256>>>(el, a1_o);
    node_attn2<<<6250, 256>>>(nl);

    gather_out<<<BATCH_C, 128>>>(bi, out);
}

// round 16
// speedup vs baseline: 1.3127x; 1.1056x over previous
#include <cuda_runtime.h>
#include <cuda_bf16.h>
#include <cstdint>

#define N_NODES_C 50000
#define N_EDGES_C 25000
#define MAX_ARITY 6
#define MAX_DEG 8
#define BATCH_C 4096

// ---------------- scratch (device globals; no allocations allowed) ----------------
__device__ __align__(256) __nv_bfloat16 g_embn[N_NODES_C * 128];
__device__ __align__(256) __nv_bfloat16 g_embe[N_EDGES_C * 128];
__device__ __align__(256) __nv_bfloat16 g_hn1[N_NODES_C * 256];
__device__ __align__(256) __nv_bfloat16 g_eo1[N_EDGES_C * 256];
__device__ __align__(256) __nv_bfloat16 g_eo1e[N_EDGES_C * 256];
__device__ __align__(256) __nv_bfloat16 g_no1[N_NODES_C * 256];
__device__ __align__(256) __nv_bfloat16 g_hn2[N_NODES_C * 128];
__device__ __align__(256) float g_eo2[N_EDGES_C * 128];
__device__ __align__(256) float g_no2[N_NODES_C * 128];
// pre-transposed bf16 weights, [n][k]
__device__ __align__(256) __nv_bfloat16 g_Bt1n[256 * 128];
__device__ __align__(256) __nv_bfloat16 g_Bt1e[256 * 128];
__device__ __align__(256) __nv_bfloat16 g_Bt2n[128 * 256];
__device__ __align__(256) __nv_bfloat16 g_Bt2e[128 * 256];
// score-weight vectors
__device__ float g_wpn1[256];
__device__ float g_wqn1[256];
__device__ float g_wpe1[256];
__device__ float g_wpn2[128];
__device__ float g_wqn2[128];
__device__ float g_wpe2[128];
// scalar score caches (unique-writer)
__device__ float g_pn1[N_NODES_C * 4];
__device__ float g_sn1[N_NODES_C * 4];
__device__ float g_se1[N_EDGES_C * 4];
__device__ float g_pe1[N_EDGES_C * 4];
__device__ float g_pn2[N_NODES_C];
__device__ float g_sn2[N_NODES_C];
__device__ float g_se2[N_EDGES_C];
__device__ float g_pe2[N_EDGES_C];
__device__ unsigned char g_mask[N_NODES_C];

// ---------------- helpers ----------------
__device__ __forceinline__ float warp_sum(float v) {
#pragma unroll
    for (int o = 16; o > 0; o >>= 1) v += __shfl_xor_sync(0xffffffffu, v, o);
    return v;
}
__device__ __forceinline__ float seg8_sum(float v) {
#pragma unroll
    for (int o = 4; o > 0; o >>= 1) v += __shfl_xor_sync(0xffffffffu, v, o);
    return v;
}
// fast-math variants: softmax weights / ELU tails tolerate ~1e-6 error
__device__ __forceinline__ float fexp(float x)  { return __expf(x); }
__device__ __forceinline__ float eluf(float x)  { return x > 0.f ? x : __expf(x) - 1.f; }
__device__ __forceinline__ float lreluf(float x){ return x > 0.f ? x : 0.2f * x; }

__device__ __forceinline__ void ldsm4(unsigned r[4], unsigned addr) {
    asm volatile("ldmatrix.sync.aligned.m8n8.x4.shared.b16 {%0,%1,%2,%3},[%4];"
                 : "=r"(r[0]), "=r"(r[1]), "=r"(r[2]), "=r"(r[3]) : "r"(addr));
}
__device__ __forceinline__ void mma16(float c[4], const unsigned a[4],
                                      unsigned b0, unsigned b1) {
    asm volatile(
        "mma.sync.aligned.m16n8k16.row.col.f32.bf16.bf16.f32 "
        "{%0,%1,%2,%3},{%4,%5,%6,%7},{%8,%9},{%0,%1,%2,%3};"
        : "+f"(c[0]), "+f"(c[1]), "+f"(c[2]), "+f"(c[3])
        : "r"(a[0]), "r"(a[1]), "r"(a[2]), "r"(a[3]), "r"(b0), "r"(b1));
}

__device__ __forceinline__ unsigned packbf(float a, float b) {
    __nv_bfloat162 h = __floats2bfloat162_rn(a, b);
    return *reinterpret_cast<unsigned*>(&h);
}
__device__ __forceinline__ float2 unpackbf(unsigned u) {
    return __bfloat1622float2(*reinterpret_cast<__nv_bfloat162*>(&u));
}
__device__ __forceinline__ void unpack8(uint4 u, float f[8]) {
    float2 a = unpackbf(u.x), b = unpackbf(u.y), c = unpackbf(u.z), d = unpackbf(u.w);
    f[0] = a.x; f[1] = a.y; f[2] = b.x; f[3] = b.y;
    f[4] = c.x; f[5] = c.y; f[6] = d.x; f[7] = d.y;
}
__device__ __forceinline__ uint4 pack8(const float f[8]) {
    uint4 u;
    u.x = packbf(f[0], f[1]); u.y = packbf(f[2], f[3]);
    u.z = packbf(f[4], f[5]); u.w = packbf(f[6], f[7]);
    return u;
}

// ---------------- prep ----------------
__global__ void prep(const float* __restrict__ Wn, const float* __restrict__ We,
                     const float* __restrict__ Wn_o, const float* __restrict__ We_o,
                     const float* __restrict__ a1, const float* __restrict__ a2,
                     const float* __restrict__ a1o, const float* __restrict__ a2o) {
    int i = blockIdx.x * 256 + threadIdx.x;
    if (i < 32768) {
        int c = i >> 7, k = i & 127;
        int h = c >> 6, j = c & 63;
        g_Bt1n[i] = __float2bfloat16_rn(Wn[h * 8192 + k * 64 + j]);
        g_Bt1e[i] = __float2bfloat16_rn(We[h * 8192 + k * 64 + j]);
        int n2 = i >> 8, k2 = i & 255;
        g_Bt2n[i] = __float2bfloat16_rn(Wn_o[k2 * 128 + n2]);
        g_Bt2e[i] = __float2bfloat16_rn(We_o[k2 * 128 + n2]);
    }
    if (i < 256) {
        int h = i >> 6, j = i & 63;
        g_wpn1[i] = a1[h * 128 + 64 + j];
        g_wqn1[i] = a2[h * 128 + j];
        g_wpe1[i] = a1[h * 128 + j];
    }
    if (i < 128) {
        g_wpn2[i] = a1o[128 + i];
        g_wqn2[i] = a2o[i];
        g_wpe2[i] = a1o[i];
    }
    if (i < N_NODES_C) g_mask[i] = 0;
}

// ---------------- convert embeddings fp32 -> bf16, and mark batch nodes ----------
__global__ void conv_emb(const float* __restrict__ nemb, const float* __restrict__ eemb,
                         const int* __restrict__ bi) {
    int i = blockIdx.x * 256 + threadIdx.x;
    if (i < (N_NODES_C * 128) / 8) {
        float4 v0 = *reinterpret_cast<const float4*>(nemb + i * 8);
        float4 v1 = *reinterpret_cast<const float4*>(nemb + i * 8 + 4);
        uint4 u;
        u.x = packbf(v0.x, v0.y); u.y = packbf(v0.z, v0.w);
        u.z = packbf(v1.x, v1.y); u.w = packbf(v1.z, v1.w);
        *reinterpret_cast<uint4*>(g_embn + i * 8) = u;
    }
    if (i < (N_EDGES_C * 128) / 8) {
        float4 v0 = *reinterpret_cast<const float4*>(eemb + i * 8);
        float4 v1 = *reinterpret_cast<const float4*>(eemb + i * 8 + 4);
        uint4 u;
        u.x = packbf(v0.x, v0.y); u.y = packbf(v0.z, v0.w);
        u.z = packbf(v1.x, v1.y); u.w = packbf(v1.z, v1.w);
        *reinterpret_cast<uint4*>(g_embe + i * 8) = u;
    }
    if (i < BATCH_C * 6) {
        int b = i / 6, a = i % 6 + 1;
        int nid = bi[b * 7 + a] - 1;
        if (nid < 0) nid += N_NODES_C;
        g_mask[nid] = 1;
    }
}

// ---------------- fused dual-problem BF16 GEMM ------------------------------------
struct GArgs {
    const __nv_bfloat16* A;
    const __nv_bfloat16* Bt;
    __nv_bfloat16* C;
    int M;
    const float* wp;
    const float* wq;
    float* P;
    float* Q;
    int writeC;
    int scores;
    int gx;
};

__global__ __launch_bounds__(256, 2)
void gemm_dual(GArgs ga1, GArgs ga2, int split, int N, int K, int PS) {
    extern __shared__ __align__(16) __nv_bfloat16 smem[];
    __nv_bfloat16* Asm = smem;                    // [6][128][24]
    __nv_bfloat16* Bsm = smem + 6 * 128 * 24;     // [6][128][24]

    const bool first = (int)blockIdx.x < split;
    const GArgs ga = first ? ga1 : ga2;
    const int bl = first ? blockIdx.x : blockIdx.x - split;
    const int bx = bl % ga.gx, by = bl / ga.gx;
    const int bm = bx * 128, bn = by * 128;

    const int tid = threadIdx.x;
    const int w = tid >> 5, lane = tid & 31;
    const int wm = (w >> 1) * 32, wn = (w & 1) * 64;
    const int gid = lane >> 2, tig = lane & 3;
    float acc[2][8][4] = {};

    const unsigned asBase = (unsigned)__cvta_generic_to_shared(Asm);
    const unsigned bsBase = (unsigned)__cvta_generic_to_shared(Bsm);
    const unsigned aoffL = (unsigned)((wm + (lane & 15)) * 48 + (lane >> 4) * 16);
    const unsigned boffL = (unsigned)((wn + ((lane >> 4) << 3) + (lane & 7)) * 48
                                      + ((lane >> 3) & 1) * 16);
    const int srow = tid >> 1, sch = tid & 1;
    const bool aval = (bm + srow) < ga.M;
    const __nv_bfloat16* Agp = ga.A + (size_t)(bm + srow) * K + sch * 8;
    const __nv_bfloat16* Bgp = ga.Bt + (size_t)(bn + srow) * K + sch * 8;
    const unsigned daBase = asBase + (unsigned)(srow * 48 + sch * 16);
    const unsigned dbBase = bsBase + (unsigned)(srow * 48 + sch * 16);
    const int aSz = aval ? 16 : 0;

    auto issuePair = [&](int p) {
        int s0 = (2 * p) % 6;
        int k0 = p * 32;
        asm volatile("cp.async.ca.shared.global [%0], [%1], 16, %2;"
                     :: "r"(daBase + s0 * 6144), "l"(Agp + k0), "r"(aSz));
        asm volatile("cp.async.ca.shared.global [%0], [%1], 16, %2;"
                     :: "r"(daBase + (s0 + 1) * 6144), "l"(Agp + k0 + 16), "r"(aSz));
        asm volatile("cp.async.ca.shared.global [%0], [%1], 16;"
                     :: "r"(dbBase + s0 * 6144), "l"(Bgp + k0));
        asm volatile("cp.async.ca.shared.global [%0], [%1], 16;"
                     :: "r"(dbBase + (s0 + 1) * 6144), "l"(Bgp + k0 + 16));
        asm volatile("cp.async.commit_group;" ::: "memory");
    };

    const int TP = K >> 5;
    issuePair(0);
    issuePair(1);

    for (int p = 0; p < TP; p++) {
        asm volatile("cp.async.wait_group 1;" ::: "memory");
        __syncthreads();
#pragma unroll
        for (int sub = 0; sub < 2; sub++) {
            const int buf = (2 * p + sub) % 6;
            unsigned af[2][4], bfr[4][4];
            unsigned ab = asBase + (unsigned)(buf * 6144) + aoffL;
            ldsm4(af[0], ab);
            ldsm4(af[1], ab + 16 * 48);
            unsigned bb = bsBase + (unsigned)(buf * 6144) + boffL;
#pragma unroll
            for (int bt = 0; bt < 4; bt++) ldsm4(bfr[bt], bb + bt * 16 * 48);
#pragma unroll
            for (int mt = 0; mt < 2; mt++)
#pragma unroll
                for (int nt = 0; nt < 8; nt++)
                    mma16(acc[mt][nt], af[mt],
                          bfr[nt >> 1][(nt & 1) * 2], bfr[nt >> 1][(nt & 1) * 2 + 1]);
        }
        if (p + 2 < TP) issuePair(p + 2);
        else asm volatile("cp.async.commit_group;" ::: "memory");
    }

    if (ga.writeC) {
        __nv_bfloat16* Cb = ga.C;
#pragma unroll
        for (int mt = 0; mt < 2; mt++) {
#pragma unroll
            for (int nt = 0; nt < 8; nt++) {
                int r0 = bm + wm + mt * 16 + gid;
                int c = bn + wn + nt * 8 + tig * 2;
                if (r0 < ga.M)
                    *reinterpret_cast<unsigned*>(Cb + (size_t)r0 * N + c) =
                        packbf(acc[mt][nt][0], acc[mt][nt][1]);
                if (r0 + 8 < ga.M)
                    *reinterpret_cast<unsigned*>(Cb + (size_t)(r0 + 8) * N + c) =
                        packbf(acc[mt][nt][2], acc[mt][nt][3]);
            }
        }
    }

    {   // fused score epilogue
        const int pidx = (PS == 4) ? ((bn + wn) >> 6) : 0;
        const bool two = (ga.scores == 2);
        float wpv[8][2], wqv[8][2];
#pragma unroll
        for (int nt = 0; nt < 8; nt++) {
            int c = bn + wn + nt * 8 + tig * 2;
            wpv[nt][0] = ga.wp[c]; wpv[nt][1] = ga.wp[c + 1];
            if (two) { wqv[nt][0] = ga.wq[c]; wqv[nt][1] = ga.wq[c + 1]; }
        }
#pragma unroll
        for (int mt = 0; mt < 2; mt++) {
#pragma unroll
            for (int half = 0; half < 2; half++) {
                float p = 0.f, q = 0.f;
#pragma unroll
                for (int nt = 0; nt < 8; nt++) {
                    p += acc[mt][nt][half * 2 + 0] * wpv[nt][0]
                       + acc[mt][nt][half * 2 + 1] * wpv[nt][1];
                    if (two)
                        q += acc[mt][nt][half * 2 + 0] * wqv[nt][0]
                           + acc[mt][nt][half * 2 + 1] * wqv[nt][1];
                }
                p += __shfl_xor_sync(0xffffffffu, p, 1);
                p += __shfl_xor_sync(0xffffffffu, p, 2);
                if (two) {
                    q += __shfl_xor_sync(0xffffffffu, q, 1);
                    q += __shfl_xor_sync(0xffffffffu, q, 2);
                }
                int r = bm + wm + mt * 16 + gid + half * 8;
                if (tig == 0 && r < ga.M) {
                    ga.P[(size_t)r * PS + pidx] = p;
                    if (two) ga.Q[(size_t)r * PS + pidx] = q;
                }
            }
        }
    }
}

// ------- layer1 edge attention: warp per edge; writes raw + ELU copies -----------
__global__ __launch_bounds__(256)
void edge_attn1(const int* __restrict__ el, const float* __restrict__ a2) {
    int e = blockIdx.x * 8 + (threadIdx.x >> 5);
    if (e >= N_EDGES_C) return;
    int lane = threadIdx.x & 31;
    int h = lane >> 3, jl = lane & 7;
    float se = g_se1[e * 4 + h];
    int ids[MAX_ARITY];
    float s[MAX_ARITY];
#pragma unroll
    for (int ai = 0; ai < MAX_ARITY; ai++) ids[ai] = el[e * MAX_ARITY + ai];
#pragma unroll
    for (int ai = 0; ai < MAX_ARITY; ai++)
        s[ai] = (ids[ai] > 0) ? lreluf(se + g_pn1[(ids[ai] - 1) * 4 + h]) : -1e9f;
    float m = s[0];
#pragma unroll
    for (int ai = 1; ai < MAX_ARITY; ai++) m = fmaxf(m, s[ai]);
    float wv[MAX_ARITY], den = 0.f;
#pragma unroll
    for (int ai = 0; ai < MAX_ARITY; ai++) { wv[ai] = fexp(s[ai] - m); den += wv[ai]; }
    float inv = 1.f / den;
    float o[8] = {};
#pragma unroll
    for (int ai = 0; ai < MAX_ARITY; ai++) {
        if (ids[ai] > 0) {
            uint4 u = *reinterpret_cast<const uint4*>(
                g_hn1 + (size_t)(ids[ai] - 1) * 256 + lane * 8);
            float f[8]; unpack8(u, f);
            float wg = wv[ai] * inv;
#pragma unroll
            for (int i = 0; i < 8; i++) o[i] += wg * f[i];
        }
    }
    *reinterpret_cast<uint4*>(g_eo1 + (size_t)e * 256 + lane * 8) = pack8(o);
    float oe[8];
#pragma unroll
    for (int i = 0; i < 8; i++) oe[i] = eluf(o[i]);
    *reinterpret_cast<uint4*>(g_eo1e + (size_t)e * 256 + lane * 8) = pack8(oe);
    float pe = 0.f;
#pragma unroll
    for (int i = 0; i < 8; i++) pe += o[i] * a2[h * 128 + 64 + jl * 8 + i];
    pe = seg8_sum(pe);
    if (jl == 0) g_pe1[e * 4 + h] = pe;
}

// ------- layer1 node attention: warp per node, +ELU ------------------------------
__global__ __launch_bounds__(256)
void node_attn1(const int* __restrict__ nl) {
    int n = blockIdx.x * 8 + (threadIdx.x >> 5);
    if (n >= N_NODES_C) return;
    int lane = threadIdx.x & 31;
    int h = lane >> 3;
    float sn = g_sn1[n * 4 + h];
    int ids[MAX_DEG];
    float s[MAX_DEG];
#pragma unroll
    for (int di = 0; di < MAX_DEG; di++) ids[di] = nl[n * MAX_DEG + di];
#pragma unroll
    for (int di = 0; di < MAX_DEG; di++)
        s[di] = (ids[di] > 0) ? lreluf(sn + g_pe1[(ids[di] - 1) * 4 + h]) : -1e9f;
    float m = s[0];
#pragma unroll
    for (int di = 1; di < MAX_DEG; di++) m = fmaxf(m, s[di]);
    float wv[MAX_DEG], den = 0.f;
#pragma unroll
    for (int di = 0; di < MAX_DEG; di++) { wv[di] = fexp(s[di] - m); den += wv[di]; }
    float inv = 1.f / den;
    float o[8] = {};
#pragma unroll
    for (int di = 0; di < MAX_DEG; di++) {
        if (ids[di] > 0) {
            uint4 u = *reinterpret_cast<const uint4*>(
                g_eo1 + (size_t)(ids[di] - 1) * 256 + lane * 8);
            float f[8]; unpack8(u, f);
            float wg = wv[di] * inv;
#pragma unroll
            for (int i = 0; i < 8; i++) o[i] += wg * f[i];
        }
    }
#pragma unroll
    for (int i = 0; i < 8; i++) o[i] = eluf(o[i]);
    *reinterpret_cast<uint4*>(g_no1 + (size_t)n * 256 + lane * 8) = pack8(o);
}

// ------- layer2 edge attention ----------------------------------------------------
__global__ __launch_bounds__(256)
void edge_attn2(const int* __restrict__ el, const float* __restrict__ a2o) {
    int e = blockIdx.x * 8 + (threadIdx.x >> 5);
    if (e >= N_EDGES_C) return;
    int lane = threadIdx.x & 31;
    float se = g_se2[e];
    int ids[MAX_ARITY];
    float s[MAX_ARITY];
#pragma unroll
    for (int ai = 0; ai < MAX_ARITY; ai++) ids[ai] = el[e * MAX_ARITY + ai];
#pragma unroll
    for (int ai = 0; ai < MAX_ARITY; ai++)
        s[ai] = (ids[ai] > 0) ? lreluf(se + g_pn2[ids[ai] - 1]) : -1e9f;
    float m = s[0];
#pragma unroll
    for (int ai = 1; ai < MAX_ARITY; ai++) m = fmaxf(m, s[ai]);
    float wv[MAX_ARITY], den = 0.f;
#pragma unroll
    for (int ai = 0; ai < MAX_ARITY; ai++) { wv[ai] = fexp(s[ai] - m); den += wv[ai]; }
    float inv = 1.f / den;
    float o[4] = {};
#pragma unroll
    for (int ai = 0; ai < MAX_ARITY; ai++) {
        if (ids[ai] > 0) {
            uint2 u = *reinterpret_cast<const uint2*>(
                g_hn2 + (size_t)(ids[ai] - 1) * 128 + lane * 4);
            float2 x = unpackbf(u.x), y = unpackbf(u.y);
            float wg = wv[ai] * inv;
            o[0] += wg * x.x; o[1] += wg * x.y; o[2] += wg * y.x; o[3] += wg * y.y;
        }
    }
    *reinterpret_cast<float4*>(g_eo2 + (size_t)e * 128 + lane * 4) =
        make_float4(o[0], o[1], o[2], o[3]);
    float pe = 0.f;
#pragma unroll
    for (int i = 0; i < 4; i++) pe += o[i] * a2o[128 + lane * 4 + i];
    pe = warp_sum(pe);
    if (lane == 0) g_pe2[e] = pe;
}

// ------- layer2 node attention: pruned to batch-referenced -----------------------
__global__ __launch_bounds__(256)
void node_attn2(const int* __restrict__ nl) {
    int n = blockIdx.x * 8 + (threadIdx.x >> 5);
    if (n >= N_NODES_C) return;
    if (!g_mask[n]) return;
    int lane = threadIdx.x & 31;
    float sn = g_sn2[n];
    int ids[MAX_DEG];
    float s[MAX_DEG];
#pragma unroll
    for (int di = 0; di < MAX_DEG; di++) ids[di] = nl[n * MAX_DEG + di];
#pragma unroll
    for (int di = 0; di < MAX_DEG; di++)
        s[di] = (ids[di] > 0) ? lreluf(sn + g_pe2[ids[di] - 1]) : -1e9f;
    float m = s[0];
#pragma unroll
    for (int di = 1; di < MAX_DEG; di++) m = fmaxf(m, s[di]);
    float wv[MAX_DEG], den = 0.f;
#pragma unroll
    for (int di = 0; di < MAX_DEG; di++) { wv[di] = fexp(s[di] - m); den += wv[di]; }
    float inv = 1.f / den;
    float o[4] = {};
#pragma unroll
    for (int di = 0; di < MAX_DEG; di++) {
        if (ids[di] > 0) {
            float4 x = *reinterpret_cast<const float4*>(
                g_eo2 + (size_t)(ids[di] - 1) * 128 + lane * 4);
            float wg = wv[di] * inv;
            o[0] += wg * x.x; o[1] += wg * x.y; o[2] += wg * x.z; o[3] += wg * x.w;
        }
    }
    *reinterpret_cast<float4*>(g_no2 + (size_t)n * 128 + lane * 4) =
        make_float4(o[0], o[1], o[2], o[3]);
}

// ---------------- final batch gather ----------------
__global__ __launch_bounds__(128)
void gather_out(const int* __restrict__ bi, float* __restrict__ out) {
    int b = blockIdx.x;
    int t = threadIdx.x;
    __shared__ int ids[7];
    __shared__ int lastnz;
    if (t < 7) ids[t] = bi[b * 7 + t];
    __syncthreads();
    if (t == 0) {
        int ln = 0;
#pragma unroll
        for (int j = 1; j < 7; j++) if (ids[j] != 0) ln = j;
        lastnz = ln;
    }
    __syncthreads();
    int ln = lastnz;
    out[(size_t)b * 896 + t] = eluf(g_eo2[(size_t)(ids[0] - 1) * 128 + t]);
#pragma unroll
    for (int a = 1; a < 7; a++) {
        int nid = ids[a] - 1;
        if (nid < 0) nid += N_NODES_C;
        float g = (a <= ln) ? eluf(g_no2[(size_t)nid * 128 + t]) : 1.0f;
        out[(size_t)b * 896 + a * 128 + t] = g;
    }
}

// ---------------- launch ----------------
extern "C" void kernel_launch(void* const* d_in, const int* in_sizes, int n_in,
                              void* d_out, int out_size) {
    (void)in_sizes; (void)n_in; (void)out_size;
    const int*   bi    = (const int*)d_in[0];
    const int*   el    = (const int*)d_in[1];
    const int*   nl    = (const int*)d_in[2];
    const float* nemb  = (const float*)d_in[3];
    const float* eemb  = (const float*)d_in[4];
    const float* Wn    = (const float*)d_in[5];
    const float* We    = (const float*)d_in[6];
    const float* a1    = (const float*)d_in[7];
    const float* a2    = (const float*)d_in[8];
    const float* Wn_o  = (const float*)d_in[9];
    const float* We_o  = (const float*)d_in[10];
    const float* a1_o  = (const float*)d_in[11];
    const float* a2_o  = (const float*)d_in[12];
    float* out = (float*)d_out;

    __nv_bfloat16 *embn, *embe, *hn1, *eo1e, *no1, *hn2;
    __nv_bfloat16 *bt1n, *bt1e, *bt2n, *bt2e;
    float *pn1, *sn1, *se1, *pn2, *sn2, *se2;
    float *wpn1, *wqn1, *wpe1, *wpn2, *wqn2, *wpe2;
    cudaGetSymbolAddress((void**)&embn, g_embn);
    cudaGetSymbolAddress((void**)&embe, g_embe);
    cudaGetSymbolAddress((void**)&hn1, g_hn1);
    cudaGetSymbolAddress((void**)&eo1e, g_eo1e);
    cudaGetSymbolAddress((void**)&no1, g_no1);
    cudaGetSymbolAddress((void**)&hn2, g_hn2);
    cudaGetSymbolAddress((void**)&pn1, g_pn1);
    cudaGetSymbolAddress((void**)&sn1, g_sn1);
    cudaGetSymbolAddress((void**)&se1, g_se1);
    cudaGetSymbolAddress((void**)&pn2, g_pn2);
    cudaGetSymbolAddress((void**)&sn2, g_sn2);
    cudaGetSymbolAddress((void**)&se2, g_se2);
    cudaGetSymbolAddress((void**)&wpn1, g_wpn1);
    cudaGetSymbolAddress((void**)&wqn1, g_wqn1);
    cudaGetSymbolAddress((void**)&wpe1, g_wpe1);
    cudaGetSymbolAddress((void**)&wpn2, g_wpn2);
    cudaGetSymbolAddress((void**)&wqn2, g_wqn2);
    cudaGetSymbolAddress((void**)&wpe2, g_wpe2);
    cudaGetSymbolAddress((void**)&bt1n, g_Bt1n);
    cudaGetSymbolAddress((void**)&bt1e, g_Bt1e);
    cudaGetSymbolAddress((void**)&bt2n, g_Bt2n);
    cudaGetSymbolAddress((void**)&bt2e, g_Bt2e);

    static bool attr_set = false;
    if (!attr_set) {
        cudaFuncSetAttribute(gemm_dual, cudaFuncAttributeMaxDynamicSharedMemorySize,
                             73728);
        attr_set = true;
    }

    prep<<<782, 256>>>(Wn, We, Wn_o, We_o, a1, a2, a1_o, a2_o);
    conv_emb<<<3125, 256>>>(nemb, eemb, bi);

    // ---- layer1: fused node+edge projection GEMMs ----
    GArgs n1{embn, bt1n, hn1, N_NODES_C, wpn1, wqn1, pn1, sn1, 1, 2, 391};
    GArgs e1{embe, bt1e, nullptr, N_EDGES_C, wpe1, nullptr, se1, nullptr, 0, 1, 196};
    gemm_dual<<<782 + 392, 256, 73728>>>(n1, e1, 782, 256, 128, 4);

    edge_attn1<<<3125, 256>>>(el, a2);
    node_attn1<<<6250, 256>>>(nl);

    // ---- layer2: fused node+edge projection GEMMs ----
    GArgs n2{no1, bt2n, hn2, N_NODES_C, wpn2, wqn2, pn2, sn2, 1, 2, 391};
    GArgs e2{eo1e, bt2e, nullptr, N_EDGES_C, wpe2, nullptr, se2, nullptr, 0, 1, 196};
    gemm_dual<<<391 + 196, 256, 73728>>>(n2, e2, 391, 128, 256, 1);

    edge_attn2<<<3125, 256>>>(el, a1_o);
    node_attn2<<<6250, 256>>>(nl);

    gather_out<<<BATCH_C, 128>>>(bi, out);
}

// round 17
// speedup vs baseline: 1.3217x; 1.0068x over previous
#include <cuda_runtime.h>
#include <cuda_bf16.h>
#include <cstdint>

#define N_NODES_C 50000
#define N_EDGES_C 25000
#define MAX_ARITY 6
#define MAX_DEG 8
#define BATCH_C 4096

// ---------------- scratch (device globals; no allocations allowed) ----------------
__device__ __align__(256) __nv_bfloat16 g_embn[N_NODES_C * 128];
__device__ __align__(256) __nv_bfloat16 g_embe[N_EDGES_C * 128];
__device__ __align__(256) __nv_bfloat16 g_hn1[N_NODES_C * 256];
__device__ __align__(256) __nv_bfloat16 g_eo1[N_EDGES_C * 256];
__device__ __align__(256) __nv_bfloat16 g_no1[N_NODES_C * 256];
__device__ __align__(256) __nv_bfloat16 g_hn2[N_NODES_C * 128];
__device__ __align__(256) float g_eo2[N_EDGES_C * 128];
__device__ __align__(256) float g_no2[N_NODES_C * 128];
// pre-transposed bf16 weights, [n][k]
__device__ __align__(256) __nv_bfloat16 g_Bt1n[256 * 128];
__device__ __align__(256) __nv_bfloat16 g_Bt1e[256 * 128];
__device__ __align__(256) __nv_bfloat16 g_Bt2n[128 * 256];
__device__ __align__(256) __nv_bfloat16 g_Bt2e[128 * 256];
// score-weight vectors
__device__ float g_wpn1[256];
__device__ float g_wqn1[256];
__device__ float g_wpe1[256];
__device__ float g_wpn2[128];
__device__ float g_wqn2[128];
__device__ float g_wpe2[128];
// scalar score caches (unique-writer)
__device__ float g_pn1[N_NODES_C * 4];
__device__ float g_sn1[N_NODES_C * 4];
__device__ float g_se1[N_EDGES_C * 4];
__device__ float g_pe1[N_EDGES_C * 4];
__device__ float g_pn2[N_NODES_C];
__device__ float g_sn2[N_NODES_C];
__device__ float g_se2[N_EDGES_C];
__device__ float g_pe2[N_EDGES_C];
// zero-initialized at module load; marking is idempotent over constant inputs
__device__ unsigned char g_mask[N_NODES_C];

// ---------------- helpers ----------------
__device__ __forceinline__ float warp_sum(float v) {
#pragma unroll
    for (int o = 16; o > 0; o >>= 1) v += __shfl_xor_sync(0xffffffffu, v, o);
    return v;
}
__device__ __forceinline__ float seg8_sum(float v) {
#pragma unroll
    for (int o = 4; o > 0; o >>= 1) v += __shfl_xor_sync(0xffffffffu, v, o);
    return v;
}
__device__ __forceinline__ float fexp(float x)  { return __expf(x); }
__device__ __forceinline__ float eluf(float x)  { return x > 0.f ? x : __expf(x) - 1.f; }
__device__ __forceinline__ float lreluf(float x){ return x > 0.f ? x : 0.2f * x; }

__device__ __forceinline__ void ldsm4(unsigned r[4], unsigned addr) {
    asm volatile("ldmatrix.sync.aligned.m8n8.x4.shared.b16 {%0,%1,%2,%3},[%4];"
                 : "=r"(r[0]), "=r"(r[1]), "=r"(r[2]), "=r"(r[3]) : "r"(addr));
}
__device__ __forceinline__ void mma16(float c[4], const unsigned a[4],
                                      unsigned b0, unsigned b1) {
    asm volatile(
        "mma.sync.aligned.m16n8k16.row.col.f32.bf16.bf16.f32 "
        "{%0,%1,%2,%3},{%4,%5,%6,%7},{%8,%9},{%0,%1,%2,%3};"
        : "+f"(c[0]), "+f"(c[1]), "+f"(c[2]), "+f"(c[3])
        : "r"(a[0]), "r"(a[1]), "r"(a[2]), "r"(a[3]), "r"(b0), "r"(b1));
}

__device__ __forceinline__ unsigned packbf(float a, float b) {
    __nv_bfloat162 h = __floats2bfloat162_rn(a, b);
    return *reinterpret_cast<unsigned*>(&h);
}
__device__ __forceinline__ float2 unpackbf(unsigned u) {
    return __bfloat1622float2(*reinterpret_cast<__nv_bfloat162*>(&u));
}
__device__ __forceinline__ unsigned elu_pair(unsigned u) {
    float2 f = unpackbf(u);
    return packbf(eluf(f.x), eluf(f.y));
}
__device__ __forceinline__ void unpack8(uint4 u, float f[8]) {
    float2 a = unpackbf(u.x), b = unpackbf(u.y), c = unpackbf(u.z), d = unpackbf(u.w);
    f[0] = a.x; f[1] = a.y; f[2] = b.x; f[3] = b.y;
    f[4] = c.x; f[5] = c.y; f[6] = d.x; f[7] = d.y;
}
__device__ __forceinline__ uint4 pack8(const float f[8]) {
    uint4 u;
    u.x = packbf(f[0], f[1]); u.y = packbf(f[2], f[3]);
    u.z = packbf(f[4], f[5]); u.w = packbf(f[6], f[7]);
    return u;
}

// ---------------- setup: weights + score vectors + emb conversion + node marks ----
__global__ void setup(const float* __restrict__ Wn, const float* __restrict__ We,
                      const float* __restrict__ Wn_o, const float* __restrict__ We_o,
                      const float* __restrict__ a1, const float* __restrict__ a2,
                      const float* __restrict__ a1o, const float* __restrict__ a2o,
                      const float* __restrict__ nemb, const float* __restrict__ eemb,
                      const int* __restrict__ bi) {
    int i = blockIdx.x * 256 + threadIdx.x;
    if (i < (N_NODES_C * 128) / 8) {
        float4 v0 = *reinterpret_cast<const float4*>(nemb + i * 8);
        float4 v1 = *reinterpret_cast<const float4*>(nemb + i * 8 + 4);
        uint4 u;
        u.x = packbf(v0.x, v0.y); u.y = packbf(v0.z, v0.w);
        u.z = packbf(v1.x, v1.y); u.w = packbf(v1.z, v1.w);
        *reinterpret_cast<uint4*>(g_embn + i * 8) = u;
    }
    if (i < (N_EDGES_C * 128) / 8) {
        float4 v0 = *reinterpret_cast<const float4*>(eemb + i * 8);
        float4 v1 = *reinterpret_cast<const float4*>(eemb + i * 8 + 4);
        uint4 u;
        u.x = packbf(v0.x, v0.y); u.y = packbf(v0.z, v0.w);
        u.z = packbf(v1.x, v1.y); u.w = packbf(v1.z, v1.w);
        *reinterpret_cast<uint4*>(g_embe + i * 8) = u;
    }
    if (i < 32768) {
        int c = i >> 7, k = i & 127;
        int h = c >> 6, j = c & 63;
        g_Bt1n[i] = __float2bfloat16_rn(Wn[h * 8192 + k * 64 + j]);
        g_Bt1e[i] = __float2bfloat16_rn(We[h * 8192 + k * 64 + j]);
        int n2 = i >> 8, k2 = i & 255;
        g_Bt2n[i] = __float2bfloat16_rn(Wn_o[k2 * 128 + n2]);
        g_Bt2e[i] = __float2bfloat16_rn(We_o[k2 * 128 + n2]);
    }
    if (i < 256) {
        int h = i >> 6, j = i & 63;
        g_wpn1[i] = a1[h * 128 + 64 + j];
        g_wqn1[i] = a2[h * 128 + j];
        g_wpe1[i] = a1[h * 128 + j];
    }
    if (i < 128) {
        g_wpn2[i] = a1o[128 + i];
        g_wqn2[i] = a2o[i];
        g_wpe2[i] = a1o[i];
    }
    if (i < BATCH_C * 6) {
        int b = i / 6, a = i % 6 + 1;
        int nid = bi[b * 7 + a] - 1;
        if (nid < 0) nid += N_NODES_C;
        g_mask[nid] = 1;   // idempotent; globals zero-initialized at load
    }
}

// ---------------- fused dual-problem BF16 GEMM ------------------------------------
// eluA: A staged via register path with ELU applied (used by L2 edge-score segment).
struct GArgs {
    const __nv_bfloat16* A;
    const __nv_bfloat16* Bt;
    __nv_bfloat16* C;
    int M;
    const float* wp;
    const float* wq;
    float* P;
    float* Q;
    int writeC;
    int scores;
    int eluA;
    int gx;
};

__global__ __launch_bounds__(256, 2)
void gemm_dual(GArgs ga1, GArgs ga2, int split, int N, int K, int PS) {
    extern __shared__ __align__(16) __nv_bfloat16 smem[];
    __nv_bfloat16* Asm = smem;                    // [6][128][24]
    __nv_bfloat16* Bsm = smem + 6 * 128 * 24;     // [6][128][24]

    const bool first = (int)blockIdx.x < split;
    const GArgs ga = first ? ga1 : ga2;
    const int bl = first ? blockIdx.x : blockIdx.x - split;
    const int bx = bl % ga.gx, by = bl / ga.gx;
    const int bm = bx * 128, bn = by * 128;

    const int tid = threadIdx.x;
    const int w = tid >> 5, lane = tid & 31;
    const int wm = (w >> 1) * 32, wn = (w & 1) * 64;
    const int gid = lane >> 2, tig = lane & 3;
    float acc[2][8][4] = {};

    const unsigned asBase = (unsigned)__cvta_generic_to_shared(Asm);
    const unsigned bsBase = (unsigned)__cvta_generic_to_shared(Bsm);
    const unsigned aoffL = (unsigned)((wm + (lane & 15)) * 48 + (lane >> 4) * 16);
    const unsigned boffL = (unsigned)((wn + ((lane >> 4) << 3) + (lane & 7)) * 48
                                      + ((lane >> 3) & 1) * 16);
    const int srow = tid >> 1, sch = tid & 1;
    const bool aval = (bm + srow) < ga.M;
    const __nv_bfloat16* Agp = ga.A + (size_t)(bm + srow) * K + sch * 8;
    const __nv_bfloat16* Bgp = ga.Bt + (size_t)(bn + srow) * K + sch * 8;
    const unsigned daBase = asBase + (unsigned)(srow * 48 + sch * 16);
    const unsigned dbBase = bsBase + (unsigned)(srow * 48 + sch * 16);
    __nv_bfloat16* AsmT = Asm + srow * 24 + sch * 8;   // generic-ptr STS target
    const int aSz = aval ? 16 : 0;
    const bool doElu = (ga.eluA != 0);

    auto stageAelu = [&](int s, int k0) {
        uint4 u = make_uint4(0u, 0u, 0u, 0u);
        if (aval) u = *reinterpret_cast<const uint4*>(Agp + k0);
        u.x = elu_pair(u.x); u.y = elu_pair(u.y);
        u.z = elu_pair(u.z); u.w = elu_pair(u.w);
        *reinterpret_cast<uint4*>(AsmT + s * 3072) = u;
    };

    auto issuePair = [&](int p) {
        int s0 = (2 * p) % 6;
        int k0 = p * 32;
        if (doElu) {
            stageAelu(s0, k0);
            stageAelu(s0 + 1, k0 + 16);
        } else {
            asm volatile("cp.async.ca.shared.global [%0], [%1], 16, %2;"
                         :: "r"(daBase + s0 * 6144), "l"(Agp + k0), "r"(aSz));
            asm volatile("cp.async.ca.shared.global [%0], [%1], 16, %2;"
                         :: "r"(daBase + (s0 + 1) * 6144), "l"(Agp + k0 + 16), "r"(aSz));
        }
        asm volatile("cp.async.ca.shared.global [%0], [%1], 16;"
                     :: "r"(dbBase + s0 * 6144), "l"(Bgp + k0));
        asm volatile("cp.async.ca.shared.global [%0], [%1], 16;"
                     :: "r"(dbBase + (s0 + 1) * 6144), "l"(Bgp + k0 + 16));
        asm volatile("cp.async.commit_group;" ::: "memory");
    };

    const int TP = K >> 5;
    issuePair(0);
    issuePair(1);

    for (int p = 0; p < TP; p++) {
        asm volatile("cp.async.wait_group 1;" ::: "memory");
        __syncthreads();
#pragma unroll
        for (int sub = 0; sub < 2; sub++) {
            const int buf = (2 * p + sub) % 6;
            unsigned af[2][4], bfr[4][4];
            unsigned ab = asBase + (unsigned)(buf * 6144) + aoffL;
            ldsm4(af[0], ab);
            ldsm4(af[1], ab + 16 * 48);
            unsigned bb = bsBase + (unsigned)(buf * 6144) + boffL;
#pragma unroll
            for (int bt = 0; bt < 4; bt++) ldsm4(bfr[bt], bb + bt * 16 * 48);
#pragma unroll
            for (int mt = 0; mt < 2; mt++)
#pragma unroll
                for (int nt = 0; nt < 8; nt++)
                    mma16(acc[mt][nt], af[mt],
                          bfr[nt >> 1][(nt & 1) * 2], bfr[nt >> 1][(nt & 1) * 2 + 1]);
        }
        if (p + 2 < TP) issuePair(p + 2);
        else asm volatile("cp.async.commit_group;" ::: "memory");
    }

    if (ga.writeC) {
        __nv_bfloat16* Cb = ga.C;
#pragma unroll
        for (int mt = 0; mt < 2; mt++) {
#pragma unroll
            for (int nt = 0; nt < 8; nt++) {
                int r0 = bm + wm + mt * 16 + gid;
                int c = bn + wn + nt * 8 + tig * 2;
                if (r0 < ga.M)
                    *reinterpret_cast<unsigned*>(Cb + (size_t)r0 * N + c) =
                        packbf(acc[mt][nt][0], acc[mt][nt][1]);
                if (r0 + 8 < ga.M)
                    *reinterpret_cast<unsigned*>(Cb + (size_t)(r0 + 8) * N + c) =
                        packbf(acc[mt][nt][2], acc[mt][nt][3]);
            }
        }
    }

    {   // fused score epilogue
        const int pidx = (PS == 4) ? ((bn + wn) >> 6) : 0;
        const bool two = (ga.scores == 2);
        float wpv[8][2], wqv[8][2];
#pragma unroll
        for (int nt = 0; nt < 8; nt++) {
            int c = bn + wn + nt * 8 + tig * 2;
            wpv[nt][0] = ga.wp[c]; wpv[nt][1] = ga.wp[c + 1];
            if (two) { wqv[nt][0] = ga.wq[c]; wqv[nt][1] = ga.wq[c + 1]; }
        }
#pragma unroll
        for (int mt = 0; mt < 2; mt++) {
#pragma unroll
            for (int half = 0; half < 2; half++) {
                float p = 0.f, q = 0.f;
#pragma unroll
                for (int nt = 0; nt < 8; nt++) {
                    p += acc[mt][nt][half * 2 + 0] * wpv[nt][0]
                       + acc[mt][nt][half * 2 + 1] * wpv[nt][1];
                    if (two)
                        q += acc[mt][nt][half * 2 + 0] * wqv[nt][0]
                           + acc[mt][nt][half * 2 + 1] * wqv[nt][1];
                }
                p += __shfl_xor_sync(0xffffffffu, p, 1);
                p += __shfl_xor_sync(0xffffffffu, p, 2);
                if (two) {
                    q += __shfl_xor_sync(0xffffffffu, q, 1);
                    q += __shfl_xor_sync(0xffffffffu, q, 2);
                }
                int r = bm + wm + mt * 16 + gid + half * 8;
                if (tig == 0 && r < ga.M) {
                    ga.P[(size_t)r * PS + pidx] = p;
                    if (two) ga.Q[(size_t)r * PS + pidx] = q;
                }
            }
        }
    }
}

// ------- layer1 edge attention: warp per edge (raw eo1 only) ---------------------
__global__ __launch_bounds__(256)
void edge_attn1(const int* __restrict__ el, const float* __restrict__ a2) {
    int e = blockIdx.x * 8 + (threadIdx.x >> 5);
    if (e >= N_EDGES_C) return;
    int lane = threadIdx.x & 31;
    int h = lane >> 3, jl = lane & 7;
    float se = g_se1[e * 4 + h];
    int ids[MAX_ARITY];
    float s[MAX_ARITY];
#pragma unroll
    for (int ai = 0; ai < MAX_ARITY; ai++) ids[ai] = el[e * MAX_ARITY + ai];
#pragma unroll
    for (int ai = 0; ai < MAX_ARITY; ai++)
        s[ai] = (ids[ai] > 0) ? lreluf(se + g_pn1[(ids[ai] - 1) * 4 + h]) : -1e9f;
    float m = s[0];
#pragma unroll
    for (int ai = 1; ai < MAX_ARITY; ai++) m = fmaxf(m, s[ai]);
    float wv[MAX_ARITY], den = 0.f;
#pragma unroll
    for (int ai = 0; ai < MAX_ARITY; ai++) { wv[ai] = fexp(s[ai] - m); den += wv[ai]; }
    float inv = 1.f / den;
    float o[8] = {};
#pragma unroll
    for (int ai = 0; ai < MAX_ARITY; ai++) {
        if (ids[ai] > 0) {
            uint4 u = *reinterpret_cast<const uint4*>(
                g_hn1 + (size_t)(ids[ai] - 1) * 256 + lane * 8);
            float f[8]; unpack8(u, f);
            float wg = wv[ai] * inv;
#pragma unroll
            for (int i = 0; i < 8; i++) o[i] += wg * f[i];
        }
    }
    *reinterpret_cast<uint4*>(g_eo1 + (size_t)e * 256 + lane * 8) = pack8(o);
    float pe = 0.f;
#pragma unroll
    for (int i = 0; i < 8; i++) pe += o[i] * a2[h * 128 + 64 + jl * 8 + i];
    pe = seg8_sum(pe);
    if (jl == 0) g_pe1[e * 4 + h] = pe;
}

// ------- layer1 node attention: warp per node, +ELU ------------------------------
__global__ __launch_bounds__(256)
void node_attn1(const int* __restrict__ nl) {
    int n = blockIdx.x * 8 + (threadIdx.x >> 5);
    if (n >= N_NODES_C) return;
    int lane = threadIdx.x & 31;
    int h = lane >> 3;
    float sn = g_sn1[n * 4 + h];
    int ids[MAX_DEG];
    float s[MAX_DEG];
#pragma unroll
    for (int di = 0; di < MAX_DEG; di++) ids[di] = nl[n * MAX_DEG + di];
#pragma unroll
    for (int di = 0; di < MAX_DEG; di++)
        s[di] = (ids[di] > 0) ? lreluf(sn + g_pe1[(ids[di] - 1) * 4 + h]) : -1e9f;
    float m = s[0];
#pragma unroll
    for (int di = 1; di < MAX_DEG; di++) m = fmaxf(m, s[di]);
    float wv[MAX_DEG], den = 0.f;
#pragma unroll
    for (int di = 0; di < MAX_DEG; di++) { wv[di] = fexp(s[di] - m); den += wv[di]; }
    float inv = 1.f / den;
    float o[8] = {};
#pragma unroll
    for (int di = 0; di < MAX_DEG; di++) {
        if (ids[di] > 0) {
            uint4 u = *reinterpret_cast<const uint4*>(
                g_eo1 + (size_t)(ids[di] - 1) * 256 + lane * 8);
            float f[8]; unpack8(u, f);
            float wg = wv[di] * inv;
#pragma unroll
            for (int i = 0; i < 8; i++) o[i] += wg * f[i];
        }
    }
#pragma unroll
    for (int i = 0; i < 8; i++) o[i] = eluf(o[i]);
    *reinterpret_cast<uint4*>(g_no1 + (size_t)n * 256 + lane * 8) = pack8(o);
}

// ------- layer2 edge attention ----------------------------------------------------
__global__ __launch_bounds__(256)
void edge_attn2(const int* __restrict__ el, const float* __restrict__ a2o) {
    int e = blockIdx.x * 8 + (threadIdx.x >> 5);
    if (e >= N_EDGES_C) return;
    int lane = threadIdx.x & 31;
    float se = g_se2[e];
    int ids[MAX_ARITY];
    float s[MAX_ARITY];
#pragma unroll
    for (int ai = 0; ai < MAX_ARITY; ai++) ids[ai] = el[e * MAX_ARITY + ai];
#pragma unroll
    for (int ai = 0; ai < MAX_ARITY; ai++)
        s[ai] = (ids[ai] > 0) ? lreluf(se + g_pn2[ids[ai] - 1]) : -1e9f;
    float m = s[0];
#pragma unroll
    for (int ai = 1; ai < MAX_ARITY; ai++) m = fmaxf(m, s[ai]);
    float wv[MAX_ARITY], den = 0.f;
#pragma unroll
    for (int ai = 0; ai < MAX_ARITY; ai++) { wv[ai] = fexp(s[ai] - m); den += wv[ai]; }
    float inv = 1.f / den;
    float o[4] = {};
#pragma unroll
    for (int ai = 0; ai < MAX_ARITY; ai++) {
        if (ids[ai] > 0) {
            uint2 u = *reinterpret_cast<const uint2*>(
                g_hn2 + (size_t)(ids[ai] - 1) * 128 + lane * 4);
            float2 x = unpackbf(u.x), y = unpackbf(u.y);
            float wg = wv[ai] * inv;
            o[0] += wg * x.x; o[1] += wg * x.y; o[2] += wg * y.x; o[3] += wg * y.y;
        }
    }
    *reinterpret_cast<float4*>(g_eo2 + (size_t)e * 128 + lane * 4) =
        make_float4(o[0], o[1], o[2], o[3]);
    float pe = 0.f;
#pragma unroll
    for (int i = 0; i < 4; i++) pe += o[i] * a2o[128 + lane * 4 + i];
    pe = warp_sum(pe);
    if (lane == 0) g_pe2[e] = pe;
}

// ------- layer2 node attention: pruned to batch-referenced -----------------------
__global__ __launch_bounds__(256)
void node_attn2(const int* __restrict__ nl) {
    int n = blockIdx.x * 8 + (threadIdx.x >> 5);
    if (n >= N_NODES_C) return;
    if (!g_mask[n]) return;
    int lane = threadIdx.x & 31;
    float sn = g_sn2[n];
    int ids[MAX_DEG];
    float s[MAX_DEG];
#pragma unroll
    for (int di = 0; di < MAX_DEG; di++) ids[di] = nl[n * MAX_DEG + di];
#pragma unroll
    for (int di = 0; di < MAX_DEG; di++)
        s[di] = (ids[di] > 0) ? lreluf(sn + g_pe2[ids[di] - 1]) : -1e9f;
    float m = s[0];
#pragma unroll
    for (int di = 1; di < MAX_DEG; di++) m = fmaxf(m, s[di]);
    float wv[MAX_DEG], den = 0.f;
#pragma unroll
    for (int di = 0; di < MAX_DEG; di++) { wv[di] = fexp(s[di] - m); den += wv[di]; }
    float inv = 1.f / den;
    float o[4] = {};
#pragma unroll
    for (int di = 0; di < MAX_DEG; di++) {
        if (ids[di] > 0) {
            float4 x = *reinterpret_cast<const float4*>(
                g_eo2 + (size_t)(ids[di] - 1) * 128 + lane * 4);
            float wg = wv[di] * inv;
            o[0] += wg * x.x; o[1] += wg * x.y; o[2] += wg * x.z; o[3] += wg * x.w;
        }
    }
    *reinterpret_cast<float4*>(g_no2 + (size_t)n * 128 + lane * 4) =
        make_float4(o[0], o[1], o[2], o[3]);
}

// ---------------- final batch gather ----------------
__global__ __launch_bounds__(128)
void gather_out(const int* __restrict__ bi, float* __restrict__ out) {
    int b = blockIdx.x;
    int t = threadIdx.x;
    __shared__ int ids[7];
    __shared__ int lastnz;
    if (t < 7) ids[t] = bi[b * 7 + t];
    __syncthreads();
    if (t == 0) {
        int ln = 0;
#pragma unroll
        for (int j = 1; j < 7; j++) if (ids[j] != 0) ln = j;
        lastnz = ln;
    }
    __syncthreads();
    int ln = lastnz;
    out[(size_t)b * 896 + t] = eluf(g_eo2[(size_t)(ids[0] - 1) * 128 + t]);
#pragma unroll
    for (int a = 1; a < 7; a++) {
        int nid = ids[a] - 1;
        if (nid < 0) nid += N_NODES_C;
        float g = (a <= ln) ? eluf(g_no2[(size_t)nid * 128 + t]) : 1.0f;
        out[(size_t)b * 896 + a * 128 + t] = g;
    }
}

// ---------------- launch ----------------
extern "C" void kernel_launch(void* const* d_in, const int* in_sizes, int n_in,
                              void* d_out, int out_size) {
    (void)in_sizes; (void)n_in; (void)out_size;
    const int*   bi    = (const int*)d_in[0];
    const int*   el    = (const int*)d_in[1];
    const int*   nl    = (const int*)d_in[2];
    const float* nemb  = (const float*)d_in[3];
    const float* eemb  = (const float*)d_in[4];
    const float* Wn    = (const float*)d_in[5];
    const float* We    = (const float*)d_in[6];
    const float* a1    = (const float*)d_in[7];
    const float* a2    = (const float*)d_in[8];
    const float* Wn_o  = (const float*)d_in[9];
    const float* We_o  = (const float*)d_in[10];
    const float* a1_o  = (const float*)d_in[11];
    const float* a2_o  = (const float*)d_in[12];
    float* out = (float*)d_out;

    __nv_bfloat16 *embn, *embe, *hn1, *eo1, *no1, *hn2;
    __nv_bfloat16 *bt1n, *bt1e, *bt2n, *bt2e;
    float *pn1, *sn1, *se1, *pn2, *sn2, *se2;
    float *wpn1, *wqn1, *wpe1, *wpn2, *wqn2, *wpe2;
    cudaGetSymbolAddress((void**)&embn, g_embn);
    cudaGetSymbolAddress((void**)&embe, g_embe);
    cudaGetSymbolAddress((void**)&hn1, g_hn1);
    cudaGetSymbolAddress((void**)&eo1, g_eo1);
    cudaGetSymbolAddress((void**)&no1, g_no1);
    cudaGetSymbolAddress((void**)&hn2, g_hn2);
    cudaGetSymbolAddress((void**)&pn1, g_pn1);
    cudaGetSymbolAddress((void**)&sn1, g_sn1);
    cudaGetSymbolAddress((void**)&se1, g_se1);
    cudaGetSymbolAddress((void**)&pn2, g_pn2);
    cudaGetSymbolAddress((void**)&sn2, g_sn2);
    cudaGetSymbolAddress((void**)&se2, g_se2);
    cudaGetSymbolAddress((void**)&wpn1, g_wpn1);
    cudaGetSymbolAddress((void**)&wqn1, g_wqn1);
    cudaGetSymbolAddress((void**)&wpe1, g_wpe1);
    cudaGetSymbolAddress((void**)&wpn2, g_wpn2);
    cudaGetSymbolAddress((void**)&wqn2, g_wqn2);
    cudaGetSymbolAddress((void**)&wpe2, g_wpe2);
    cudaGetSymbolAddress((void**)&bt1n, g_Bt1n);
    cudaGetSymbolAddress((void**)&bt1e, g_Bt1e);
    cudaGetSymbolAddress((void**)&bt2n, g_Bt2n);
    cudaGetSymbolAddress((void**)&bt2e, g_Bt2e);

    static bool attr_set = false;
    if (!attr_set) {
        cudaFuncSetAttribute(gemm_dual, cudaFuncAttributeMaxDynamicSharedMemorySize,
                             73728);
        attr_set = true;
    }

    setup<<<3125, 256>>>(Wn, We, Wn_o, We_o, a1, a2, a1_o, a2_o, nemb, eemb, bi);

    // ---- layer1: fused node+edge projection GEMMs ----
    GArgs n1{embn, bt1n, hn1, N_NODES_C, wpn1, wqn1, pn1, sn1, 1, 2, 0, 391};
    GArgs e1{embe, bt1e, nullptr, N_EDGES_C, wpe1, nullptr, se1, nullptr, 0, 1, 0, 196};
    gemm_dual<<<782 + 392, 256, 73728>>>(n1, e1, 782, 256, 128, 4);

    edge_attn1<<<3125, 256>>>(el, a2);
    node_attn1<<<6250, 256>>>(nl);

    // ---- layer2: node GEMM + edge-score GEMM (A = raw eo1, ELU applied on load) ----
    GArgs n2{no1, bt2n, hn2, N_NODES_C, wpn2, wqn2, pn2, sn2, 1, 2, 0, 391};
    GArgs e2{eo1, bt2e, nullptr, N_EDGES_C, wpe2, nullptr, se2, nullptr, 0, 1, 1, 196};
    gemm_dual<<<391 + 196, 256, 73728>>>(n2, e2, 391, 128, 256, 1);

    edge_attn2<<<3125, 256>>>(el, a1_o);
    node_attn2<<<6250, 256>>>(nl);

    gather_out<<<BATCH_C, 128>>>(bi, out);
}